// round 11
// baseline (speedup 1.0000x reference)
#include <cuda_runtime.h>
#include <cuda_bf16.h>
#include <math.h>
#include <stdint.h>

constexpr int Dm = 1024;   // dim == seq len L
constexpr int Ns = 16;     // SSM state size
constexpr int KC = 3 * Dm; // conv GEMM K = 3072

typedef __nv_bfloat16 bf16;

// ---------------- scratch (static device globals: allocation-free) ----------
__device__ bf16 g_xhi[2 * Dm * Dm], g_xlo[2 * Dm * Dm];
__device__ bf16 g_Wphi[Dm * Dm],   g_Wplo[Dm * Dm];
__device__ bf16 g_cwhi[Dm * KC],   g_cwlo[Dm * KC];
__device__ bf16 g_WdThi[Dm * Dm],  g_WdTlo[Dm * Dm];
__device__ float g_p0[Dm * Dm];
__device__ bf16 g_xghi[Dm * Dm],   g_xglo[Dm * Dm];
__device__ bf16 g_cBhi[Dm * KC],   g_cBlo[Dm * KC];
__device__ float g_xc[Dm * Dm];
__device__ bf16 g_xchi[Dm * Dm],   g_xclo[Dm * Dm];
__device__ float g_delta[Dm * Dm];
__device__ float g_Bm[Dm * Ns], g_Cm[Dm * Ns];
__device__ bf16 g_yhi[Dm * Dm],    g_ylo[Dm * Dm];
__device__ bf16 g_thi[Dm * Dm],    g_tlo[Dm * Dm];

__device__ __forceinline__ float sigmoidf_(float x) {
    return 1.0f / (1.0f + expf(-x));
}

__device__ __forceinline__ uint32_t smem_u32(const void* p) {
    uint32_t a;
    asm("{ .reg .u64 t; cvta.to.shared.u64 t, %1; cvt.u32.u64 %0, t; }" : "=r"(a) : "l"(p));
    return a;
}

#define SWZ(x) ((x) ^ (((x) >> 3) & 0x70))

__device__ __forceinline__ void cpa16(uint32_t dst, const void* src) {
    asm volatile("cp.async.cg.shared.global [%0], [%1], 16;" :: "r"(dst), "l"(src));
}

#define MMA_BF16(c, a, b0, b1)                                                   \
    asm volatile(                                                                \
        "mma.sync.aligned.m16n8k16.row.col.f32.bf16.bf16.f32 "                   \
        "{%0,%1,%2,%3},{%4,%5,%6,%7},{%8,%9},{%0,%1,%2,%3};"                     \
        : "+f"(c[0]), "+f"(c[1]), "+f"(c[2]), "+f"(c[3])                         \
        : "r"(a[0]), "r"(a[1]), "r"(a[2]), "r"(a[3]), "r"(b0), "r"(b1))

#define LDSM_X4(r0, r1, r2, r3, addr)                                            \
    asm volatile("ldmatrix.sync.aligned.m8n8.x4.shared.b16 {%0,%1,%2,%3}, [%4];" \
        : "=r"(r0), "=r"(r1), "=r"(r2), "=r"(r3) : "r"(addr))

// ---------------- fp32 -> (hi,lo) bf16 split (vectorized 16B stores) --------
__global__ void __launch_bounds__(256) split_k(const float* __restrict__ in,
                                               bf16* __restrict__ hi,
                                               bf16* __restrict__ lo, int n) {
    int i = (blockIdx.x * 256 + threadIdx.x) * 8;
    if (i >= n) return;
    float4 v0 = *(const float4*)(in + i);
    float4 v1 = *(const float4*)(in + i + 4);
    float vv[8] = {v0.x, v0.y, v0.z, v0.w, v1.x, v1.y, v1.z, v1.w};
    __nv_bfloat162 hb[4], lb[4];
#pragma unroll
    for (int j = 0; j < 4; j++) {
        bf16 h0 = __float2bfloat16(vv[2 * j]);
        bf16 h1 = __float2bfloat16(vv[2 * j + 1]);
        hb[j].x = h0; hb[j].y = h1;
        lb[j].x = __float2bfloat16(vv[2 * j] - __bfloat162float(h0));
        lb[j].y = __float2bfloat16(vv[2 * j + 1] - __bfloat162float(h1));
    }
    *(int4*)(hi + i) = *(int4*)hb;
    *(int4*)(lo + i) = *(int4*)lb;
}

// ---------------- transpose + split (for W_delta) ---------------------------
__global__ void __launch_bounds__(256) transpose_split_k(const float* __restrict__ In,
                                                         bf16* __restrict__ hi,
                                                         bf16* __restrict__ lo) {
    __shared__ float t[32][33];
    int x0 = blockIdx.x * 32, y0 = blockIdx.y * 32;
    int tx = threadIdx.x;
    for (int j = threadIdx.y; j < 32; j += 8)
        t[j][tx] = In[(y0 + j) * Dm + x0 + tx];
    __syncthreads();
    for (int j = threadIdx.y; j < 32; j += 8) {
        float v = t[tx][j];
        bf16 h = __float2bfloat16(v);
        size_t idx = (size_t)(x0 + j) * Dm + y0 + tx;
        hi[idx] = h;
        lo[idx] = __float2bfloat16(v - __bfloat162float(h));
    }
}

// ---------------- build conv B matrix: B[d, i*3+kk] = p0[i, d-1+kk] ----------
__global__ void __launch_bounds__(256) conv_b_build(const float* __restrict__ P0,
                                                    bf16* __restrict__ hi,
                                                    bf16* __restrict__ lo) {
    __shared__ float Xs[32][35];
    int d0 = blockIdx.x * 32, i0 = blockIdx.y * 32;
    int tid = threadIdx.x;
    for (int idx = tid; idx < 32 * 34; idx += 256) {
        int r = idx / 34, c = idx % 34;
        int gd = d0 - 1 + c;
        Xs[r][c] = (gd >= 0 && gd < Dm) ? P0[(size_t)(i0 + r) * Dm + gd] : 0.0f;
    }
    __syncthreads();
    int i = tid & 31;
    for (int dl = tid >> 5; dl < 32; dl += 8) {
        size_t base = (size_t)(d0 + dl) * KC + (size_t)(i0 + i) * 3;
#pragma unroll
        for (int kk = 0; kk < 3; kk++) {
            float x = Xs[i][dl + kk];
            bf16 h = __float2bfloat16(x);
            hi[base + kk] = h;
            lo[base + kk] = __float2bfloat16(x - __bfloat162float(h));
        }
    }
}

// ---------------- bf16-split HMMA GEMM, deep cp.async pipeline ---------------
// C[m,n] = sum_k A[m,k]*B[n,k]; A=Ah+Al, B=Bh+Bl; C ~= Ah*Bh + Ah*Bl + Al*Bh.
// NT threads, CTA tile TM x TN, K-block 64, NBUF buffers, 1 barrier/stage.
// kstep phase staggered per warp so LDSM (smem pipe) and HMMA (tensor pipe)
// from co-resident warps overlap instead of bursting in lockstep.
template <int NT, int TM, int TN, int EPI, bool BIASROW, bool WF32, bool WSPLIT,
          bool DUAL>
__global__ void __launch_bounds__(NT, 1)
gemm_mma(const bf16* __restrict__ Ah, const bf16* __restrict__ Al,
         const bf16* __restrict__ Bh, const bf16* __restrict__ Bl,
         const float* __restrict__ bias,
         float* __restrict__ Cf, bf16* __restrict__ Chi, bf16* __restrict__ Clo,
         int Nn, int K)
{
    constexpr int OFF_AL = TM * 128;
    constexpr int OFF_BH = TM * 256;
    constexpr int BHL = TN * 128;
    constexpr int STAGEB = (TM + TN) * 256;
    constexpr int NBUF = (STAGEB >= 65536) ? 3 : 4;
    constexpr int DEPTH = NBUF - 1;
    constexpr int WARPS_M = TM / 32;
    constexpr int NWARP = NT / 32;
    constexpr int WN = TN / (NWARP / WARPS_M);
    constexpr int NG = WN / 16;
    constexpr int NJ = WN / 8;

    extern __shared__ __align__(1024) char dyns[];
    const int tid = threadIdx.x;
    const int lane = tid & 31, warp = tid >> 5;
    const int m0 = blockIdx.y * TM, n0 = blockIdx.x * TN;
    const uint32_t dbase = smem_u32(dyns);
    const int S = K >> 6;
    const int kofs = warp & 3;     // per-warp kstep phase offset

    float acc[2][NJ][4];
#pragma unroll
    for (int a = 0; a < 2; a++)
#pragma unroll
        for (int b = 0; b < NJ; b++)
#pragma unroll
            for (int c = 0; c < 4; c++) acc[a][b][c] = 0.0f;

    auto load_stage = [&](int s) {
        const uint32_t sb = dbase + (s % NBUF) * STAGEB;
        const int k0 = s << 6;
#pragma unroll
        for (int i = 0; i < TM * 8 / NT; i++) {
            int q = tid + i * NT;
            int r = q >> 3, c = q & 7;
            uint32_t so = SWZ((uint32_t)(r * 128 + c * 16));
            size_t ga = (size_t)(m0 + r) * K + k0 + c * 8;
            cpa16(sb + so, Ah + ga);
            cpa16(sb + OFF_AL + so, Al + ga);
        }
#pragma unroll
        for (int i = 0; i < TN * 8 / NT; i++) {
            int q = tid + i * NT;
            int r = q >> 3, c = q & 7;
            uint32_t so = SWZ((uint32_t)(r * 128 + c * 16));
            size_t gb = (size_t)(n0 + r) * K + k0 + c * 8;
            cpa16(sb + OFF_BH + so, Bh + gb);
            cpa16(sb + OFF_BH + BHL + so, Bl + gb);
        }
        asm volatile("cp.async.commit_group;" ::: "memory");
    };

#pragma unroll
    for (int s = 0; s < DEPTH; s++) load_stage(s);

    const int wm = (warp % WARPS_M) * 32, wn = (warp / WARPS_M) * WN;
    const uint32_t frow = (lane & 7) + ((lane >> 3) & 1) * 8;
    const uint32_t fxor = (frow & 7) << 4;
    const uint32_t fcol = (lane >> 4) << 4;

    for (int s = 0; s < S; s++) {
        asm volatile("cp.async.wait_group %0;" :: "n"(DEPTH - 1) : "memory");
        __syncthreads();
        if (s + DEPTH < S) load_stage(s + DEPTH);
        else asm volatile("cp.async.commit_group;" ::: "memory");

        const uint32_t sb = dbase + (s % NBUF) * STAGEB;
#pragma unroll
        for (int ks0 = 0; ks0 < 4; ks0++) {
            const int ks = (ks0 + kofs) & 3;   // staggered phase
            const uint32_t kc = (uint32_t)(ks * 32 + fcol) ^ fxor;
            uint32_t ahb[2][4], alb[2][4], bhb[NG][4], blb[NG][4];
#pragma unroll
            for (int mi = 0; mi < 2; mi++) {
                uint32_t ra = sb + (wm + mi * 16 + frow) * 128 + kc;
                LDSM_X4(ahb[mi][0], ahb[mi][1], ahb[mi][2], ahb[mi][3], ra);
                LDSM_X4(alb[mi][0], alb[mi][1], alb[mi][2], alb[mi][3], ra + OFF_AL);
            }
#pragma unroll
            for (int ni = 0; ni < NG; ni++) {
                uint32_t rb = sb + OFF_BH + (wn + ni * 16 + frow) * 128 + kc;
                LDSM_X4(bhb[ni][0], bhb[ni][1], bhb[ni][2], bhb[ni][3], rb);
                LDSM_X4(blb[ni][0], blb[ni][1], blb[ni][2], blb[ni][3], rb + BHL);
            }
#pragma unroll
            for (int mi = 0; mi < 2; mi++)
#pragma unroll
                for (int nj = 0; nj < NJ; nj++)
                    MMA_BF16(acc[mi][nj], ahb[mi], bhb[nj >> 1][nj & 1], bhb[nj >> 1][(nj & 1) + 2]);
#pragma unroll
            for (int mi = 0; mi < 2; mi++)
#pragma unroll
                for (int nj = 0; nj < NJ; nj++)
                    MMA_BF16(acc[mi][nj], ahb[mi], blb[nj >> 1][nj & 1], blb[nj >> 1][(nj & 1) + 2]);
#pragma unroll
            for (int mi = 0; mi < 2; mi++)
#pragma unroll
                for (int nj = 0; nj < NJ; nj++)
                    MMA_BF16(acc[mi][nj], alb[mi], bhb[nj >> 1][nj & 1], bhb[nj >> 1][(nj & 1) + 2]);
        }
    }

    // ---------------- epilogue ------------------------------------------------
    const int gr = lane >> 2, gc = lane & 3;
    const bool second = DUAL && (m0 >= Dm);
#pragma unroll
    for (int mi = 0; mi < 2; mi++) {
#pragma unroll
        for (int half = 0; half < 2; half++) {
            const int m = m0 + wm + mi * 16 + gr + half * 8;
            const int mrow = second ? (m - Dm) : m;
            float bm = 0.0f;
            if ((EPI == 1 || EPI == 2) && BIASROW) bm = bias[m];
#pragma unroll
            for (int nj = 0; nj < NJ; nj++) {
                const int n = n0 + wn + nj * 8 + 2 * gc;
                float v0 = acc[mi][nj][half * 2 + 0];
                float v1 = acc[mi][nj][half * 2 + 1];
                if (EPI == 1 || EPI == 2) {
                    if (BIASROW) { v0 += bm; v1 += bm; }
                    else         { v0 += bias[n]; v1 += bias[n + 1]; }
                }
                if (EPI == 2 || (DUAL && second)) {
                    v0 *= sigmoidf_(v0); v1 *= sigmoidf_(v1);
                }
                if (EPI == 3) {
                    v0 = fmaxf(v0, 0.0f) + log1pf(expf(-fabsf(v0)));
                    v1 = fmaxf(v1, 0.0f) + log1pf(expf(-fabsf(v1)));
                }
                size_t idx = (size_t)mrow * Nn + n;
                const bool wf = WF32 && !(DUAL && second);
                const bool ws = (WSPLIT && !DUAL) || (DUAL && second);
                if (wf) *(float2*)&Cf[idx] = make_float2(v0, v1);
                if (ws) {
                    bf16 h0 = __float2bfloat16(v0);
                    bf16 h1 = __float2bfloat16(v1);
                    __nv_bfloat162 hh; hh.x = h0; hh.y = h1;
                    __nv_bfloat162 ll;
                    ll.x = __float2bfloat16(v0 - __bfloat162float(h0));
                    ll.y = __float2bfloat16(v1 - __bfloat162float(h1));
                    *(__nv_bfloat162*)&Chi[idx] = hh;
                    *(__nv_bfloat162*)&Clo[idx] = ll;
                }
            }
        }
    }
}

// ---------------- B/C projections: [L,D] @ [D,16] ---------------------------
__global__ void __launch_bounds__(256) bc_kernel(const float* __restrict__ Xc,
                                                 const float* __restrict__ WB,
                                                 const float* __restrict__ WC,
                                                 float* __restrict__ Bo,
                                                 float* __restrict__ Co) {
    __shared__ float row[Dm];
    const int l = blockIdx.x;
    for (int k = threadIdx.x; k < Dm; k += 256) row[k] = Xc[(size_t)l * Dm + k];
    __syncthreads();
    const int part = threadIdx.x & 7;
    const int out = threadIdx.x >> 3;   // 0..31
    const int n = out & 15;
    const float* W = (out < 16) ? WB : WC;
    float s = 0.0f;
    for (int k = part; k < Dm; k += 8) s = fmaf(row[k], W[k * Ns + n], s);
#pragma unroll
    for (int off = 4; off; off >>= 1) s += __shfl_down_sync(0xffffffffu, s, off, 8);
    if (part == 0) {
        if (out < 16) Bo[l * Ns + n] = s;
        else          Co[l * Ns + n] = s;
    }
}

// ---------------- selective scan (__expf + load prefetch) --------------------
// Thread per (d,n): grid 128 x 128 threads (8 d x 16 n per block).
__global__ void __launch_bounds__(128) scan_kernel(const float* __restrict__ delta,
                                                   const float* __restrict__ Xc,
                                                   const float* __restrict__ Bm,
                                                   const float* __restrict__ Cm,
                                                   const float* __restrict__ Alog,
                                                   bf16* __restrict__ Yhi,
                                                   bf16* __restrict__ Ylo) {
    const int n = threadIdx.x & 15;
    const int d = blockIdx.x * 8 + (threadIdx.x >> 4);
    const float a = -expf(Alog[d * Ns + n]);
    float h = 0.0f;

    float de = delta[d];
    float xv = Xc[d];
    float bv = Bm[n];
    float cv = Cm[n];

    for (int l = 0; l < Dm; l++) {
        const size_t ix = (size_t)l * Dm + d;
        float de_n = 0.f, xv_n = 0.f, bv_n = 0.f, cv_n = 0.f;
        if (l + 1 < Dm) {
            const size_t ixn = ix + Dm;
            de_n = delta[ixn];
            xv_n = Xc[ixn];
            bv_n = Bm[(l + 1) * Ns + n];
            cv_n = Cm[(l + 1) * Ns + n];
        }
        float e = __expf(de * a);
        h = fmaf(e, h, de * xv * bv);
        float pr = h * cv;
#pragma unroll
        for (int off = 8; off; off >>= 1)
            pr += __shfl_down_sync(0xffffffffu, pr, off, 16);
        if (n == 0) {
            bf16 hh = __float2bfloat16(pr);
            Yhi[ix] = hh;
            Ylo[ix] = __float2bfloat16(pr - __bfloat162float(hh));
        }
        de = de_n; xv = xv_n; bv = bv_n; cv = cv_n;
    }
}

// ---------------- launch ------------------------------------------------------
extern "C" void kernel_launch(void* const* d_in, const int* in_sizes, int n_in,
                              void* d_out, int out_size) {
    const float* x    = (const float*)d_in[0];
    const float* Wp   = (const float*)d_in[1];
    const float* bp   = (const float*)d_in[2];
    const float* cw   = (const float*)d_in[3];
    const float* cb   = (const float*)d_in[4];
    const float* Alog = (const float*)d_in[5];
    const float* Wd   = (const float*)d_in[6];
    const float* WB   = (const float*)d_in[7];
    const float* WC   = (const float*)d_in[8];
    float* out = (float*)d_out;

    bf16 *xhi, *xlo, *Wphi, *Wplo, *cwhi, *cwlo, *WdThi, *WdTlo;
    bf16 *xghi, *xglo, *cBhi, *cBlo, *xchi, *xclo, *yhi, *ylo, *thi, *tlo;
    float *p0, *xc, *del, *Bm, *Cm;
    cudaGetSymbolAddress((void**)&xhi, g_xhi);   cudaGetSymbolAddress((void**)&xlo, g_xlo);
    cudaGetSymbolAddress((void**)&Wphi, g_Wphi); cudaGetSymbolAddress((void**)&Wplo, g_Wplo);
    cudaGetSymbolAddress((void**)&cwhi, g_cwhi); cudaGetSymbolAddress((void**)&cwlo, g_cwlo);
    cudaGetSymbolAddress((void**)&WdThi, g_WdThi); cudaGetSymbolAddress((void**)&WdTlo, g_WdTlo);
    cudaGetSymbolAddress((void**)&xghi, g_xghi); cudaGetSymbolAddress((void**)&xglo, g_xglo);
    cudaGetSymbolAddress((void**)&cBhi, g_cBhi); cudaGetSymbolAddress((void**)&cBlo, g_cBlo);
    cudaGetSymbolAddress((void**)&xchi, g_xchi); cudaGetSymbolAddress((void**)&xclo, g_xclo);
    cudaGetSymbolAddress((void**)&yhi, g_yhi);   cudaGetSymbolAddress((void**)&ylo, g_ylo);
    cudaGetSymbolAddress((void**)&thi, g_thi);   cudaGetSymbolAddress((void**)&tlo, g_tlo);
    cudaGetSymbolAddress((void**)&p0, g_p0);
    cudaGetSymbolAddress((void**)&xc, g_xc);
    cudaGetSymbolAddress((void**)&del, g_delta);
    cudaGetSymbolAddress((void**)&Bm, g_Bm);
    cudaGetSymbolAddress((void**)&Cm, g_Cm);

    const int SMEM128 = 3 * 65536;  // proj: TM=128,TN=128, 3 buffers
    const int SMEM64  = 4 * 49152;  // squares: TM=128,TN=64, 4 buffers
    cudaFuncSetAttribute(gemm_mma<512, 128, 128, 1, false, true,  true,  true>,  cudaFuncAttributeMaxDynamicSharedMemorySize, SMEM128);
    cudaFuncSetAttribute(gemm_mma<256, 128, 64,  2, true,  true,  true,  false>, cudaFuncAttributeMaxDynamicSharedMemorySize, SMEM64);
    cudaFuncSetAttribute(gemm_mma<256, 128, 64,  3, false, true,  false, false>, cudaFuncAttributeMaxDynamicSharedMemorySize, SMEM64);
    cudaFuncSetAttribute(gemm_mma<256, 128, 64,  0, false, false, true,  false>, cudaFuncAttributeMaxDynamicSharedMemorySize, SMEM64);
    cudaFuncSetAttribute(gemm_mma<256, 128, 64,  1, false, true,  false, false>, cudaFuncAttributeMaxDynamicSharedMemorySize, SMEM64);

    // #1..#3: splits needed by the proj GEMM
    split_k<<<(2 * Dm * Dm) / 2048, 256>>>(x, xhi, xlo, 2 * Dm * Dm);
    split_k<<<(Dm * Dm) / 2048, 256>>>(Wp, Wphi, Wplo, Dm * Dm);
    transpose_split_k<<<dim3(32, 32), dim3(32, 8)>>>(Wd, WdThi, WdTlo);

    // #4 (ncu slot, control): fused input projections, M=2048, 128x128, 512 thr
    gemm_mma<512, 128, 128, 1, false, true, true, true><<<dim3(8, 16), 512, SMEM128>>>(
        xhi, xlo, Wphi, Wplo, bp, p0, xghi, xglo, Dm, Dm);

    // conv operand prep
    split_k<<<(Dm * KC) / 2048, 256>>>(cw, cwhi, cwlo, Dm * KC);
    conv_b_build<<<dim3(32, 32), 256>>>(p0, cBhi, cBlo);

    // conv as GEMM (K = 3072), 128x64 tiles, 256 thr
    gemm_mma<256, 128, 64, 2, true, true, true, false><<<dim3(16, 8), 256, SMEM64>>>(
        cwhi, cwlo, cBhi, cBlo, cb, xc, xchi, xclo, Dm, KC);

    // delta = softplus(xc @ W_delta)
    gemm_mma<256, 128, 64, 3, false, true, false, false><<<dim3(16, 8), 256, SMEM64>>>(
        xchi, xclo, WdThi, WdTlo, nullptr, del, nullptr, nullptr, Dm, Dm);

    // B, C projections + scan
    bc_kernel<<<Dm, 256>>>(xc, WB, WC, Bm, Cm);
    scan_kernel<<<Dm / 8, 128>>>(del, xc, Bm, Cm, Alog, yhi, ylo);

    // t = y @ xg^T
    gemm_mma<256, 128, 64, 0, false, false, true, false><<<dim3(16, 8), 256, SMEM64>>>(
        yhi, ylo, xghi, xglo, nullptr, nullptr, thi, tlo, Dm, Dm);

    // out = t @ Wp^T + b
    gemm_mma<256, 128, 64, 1, false, true, false, false><<<dim3(16, 8), 256, SMEM64>>>(
        thi, tlo, Wphi, Wplo, bp, out, nullptr, nullptr, Dm, Dm);
}

// round 12
// speedup vs baseline: 1.1900x; 1.1900x over previous
#include <cuda_runtime.h>
#include <cuda_bf16.h>
#include <math.h>
#include <stdint.h>

constexpr int Dm = 1024;   // dim == seq len L
constexpr int Ns = 16;     // SSM state size
constexpr int KC = 3 * Dm; // conv GEMM K = 3072

typedef __nv_bfloat16 bf16;

// ---------------- scratch (static device globals: allocation-free) ----------
__device__ bf16 g_xhi[2 * Dm * Dm], g_xlo[2 * Dm * Dm];
__device__ bf16 g_Wphi[Dm * Dm],   g_Wplo[Dm * Dm];
__device__ bf16 g_cwhi[Dm * KC],   g_cwlo[Dm * KC];
__device__ bf16 g_WdThi[Dm * Dm],  g_WdTlo[Dm * Dm];
__device__ float g_p0[Dm * Dm];
__device__ bf16 g_xghi[Dm * Dm],   g_xglo[Dm * Dm];
__device__ bf16 g_cBhi[Dm * KC],   g_cBlo[Dm * KC];
__device__ float g_xc[Dm * Dm];
__device__ bf16 g_xchi[Dm * Dm],   g_xclo[Dm * Dm];
__device__ float g_delta[Dm * Dm];
__device__ float g_Bm[Dm * Ns], g_Cm[Dm * Ns];
__device__ bf16 g_yhi[Dm * Dm],    g_ylo[Dm * Dm];
__device__ bf16 g_thi[Dm * Dm],    g_tlo[Dm * Dm];

__device__ __forceinline__ float sigmoidf_(float x) {
    return 1.0f / (1.0f + expf(-x));
}

__device__ __forceinline__ uint32_t smem_u32(const void* p) {
    uint32_t a;
    asm("{ .reg .u64 t; cvta.to.shared.u64 t, %1; cvt.u32.u64 %0, t; }" : "=r"(a) : "l"(p));
    return a;
}

#define SWZ(x) ((x) ^ (((x) >> 3) & 0x70))

__device__ __forceinline__ void cpa16(uint32_t dst, const void* src) {
    asm volatile("cp.async.cg.shared.global [%0], [%1], 16;" :: "r"(dst), "l"(src));
}

#define MMA_BF16(c, a, b0, b1)                                                   \
    asm volatile(                                                                \
        "mma.sync.aligned.m16n8k16.row.col.f32.bf16.bf16.f32 "                   \
        "{%0,%1,%2,%3},{%4,%5,%6,%7},{%8,%9},{%0,%1,%2,%3};"                     \
        : "+f"(c[0]), "+f"(c[1]), "+f"(c[2]), "+f"(c[3])                         \
        : "r"(a[0]), "r"(a[1]), "r"(a[2]), "r"(a[3]), "r"(b0), "r"(b1))

#define LDSM_X4(r0, r1, r2, r3, addr)                                            \
    asm volatile("ldmatrix.sync.aligned.m8n8.x4.shared.b16 {%0,%1,%2,%3}, [%4];" \
        : "=r"(r0), "=r"(r1), "=r"(r2), "=r"(r3) : "r"(addr))

// ---------------- fp32 -> (hi,lo) bf16 split (vectorized 16B stores) --------
__global__ void __launch_bounds__(256) split_k(const float* __restrict__ in,
                                               bf16* __restrict__ hi,
                                               bf16* __restrict__ lo, int n) {
    int i = (blockIdx.x * 256 + threadIdx.x) * 8;
    if (i >= n) return;
    float4 v0 = *(const float4*)(in + i);
    float4 v1 = *(const float4*)(in + i + 4);
    float vv[8] = {v0.x, v0.y, v0.z, v0.w, v1.x, v1.y, v1.z, v1.w};
    __nv_bfloat162 hb[4], lb[4];
#pragma unroll
    for (int j = 0; j < 4; j++) {
        bf16 h0 = __float2bfloat16(vv[2 * j]);
        bf16 h1 = __float2bfloat16(vv[2 * j + 1]);
        hb[j].x = h0; hb[j].y = h1;
        lb[j].x = __float2bfloat16(vv[2 * j] - __bfloat162float(h0));
        lb[j].y = __float2bfloat16(vv[2 * j + 1] - __bfloat162float(h1));
    }
    *(int4*)(hi + i) = *(int4*)hb;
    *(int4*)(lo + i) = *(int4*)lb;
}

// ---------------- transpose + split (for W_delta) ---------------------------
__global__ void __launch_bounds__(256) transpose_split_k(const float* __restrict__ In,
                                                         bf16* __restrict__ hi,
                                                         bf16* __restrict__ lo) {
    __shared__ float t[32][33];
    int x0 = blockIdx.x * 32, y0 = blockIdx.y * 32;
    int tx = threadIdx.x;
    for (int j = threadIdx.y; j < 32; j += 8)
        t[j][tx] = In[(y0 + j) * Dm + x0 + tx];
    __syncthreads();
    for (int j = threadIdx.y; j < 32; j += 8) {
        float v = t[tx][j];
        bf16 h = __float2bfloat16(v);
        size_t idx = (size_t)(x0 + j) * Dm + y0 + tx;
        hi[idx] = h;
        lo[idx] = __float2bfloat16(v - __bfloat162float(h));
    }
}

// ---------------- build conv B matrix: B[d, i*3+kk] = p0[i, d-1+kk] ----------
__global__ void __launch_bounds__(256) conv_b_build(const float* __restrict__ P0,
                                                    bf16* __restrict__ hi,
                                                    bf16* __restrict__ lo) {
    __shared__ float Xs[32][35];
    int d0 = blockIdx.x * 32, i0 = blockIdx.y * 32;
    int tid = threadIdx.x;
    for (int idx = tid; idx < 32 * 34; idx += 256) {
        int r = idx / 34, c = idx % 34;
        int gd = d0 - 1 + c;
        Xs[r][c] = (gd >= 0 && gd < Dm) ? P0[(size_t)(i0 + r) * Dm + gd] : 0.0f;
    }
    __syncthreads();
    int i = tid & 31;
    for (int dl = tid >> 5; dl < 32; dl += 8) {
        size_t base = (size_t)(d0 + dl) * KC + (size_t)(i0 + i) * 3;
#pragma unroll
        for (int kk = 0; kk < 3; kk++) {
            float x = Xs[i][dl + kk];
            bf16 h = __float2bfloat16(x);
            hi[base + kk] = h;
            lo[base + kk] = __float2bfloat16(x - __bfloat162float(h));
        }
    }
}

// ---------------- bf16-split HMMA GEMM, deep cp.async pipeline ---------------
// C[m,n] = sum_k A[m,k]*B[n,k]; A=Ah+Al, B=Bh+Bl; C ~= Ah*Bh + Ah*Bl + Al*Bh.
// NT threads, CTA tile TM x TN, K-block 64, NBUF buffers, 1 barrier/stage.
template <int NT, int TM, int TN, int EPI, bool BIASROW, bool WF32, bool WSPLIT,
          bool DUAL>
__global__ void __launch_bounds__(NT, 1)
gemm_mma(const bf16* __restrict__ Ah, const bf16* __restrict__ Al,
         const bf16* __restrict__ Bh, const bf16* __restrict__ Bl,
         const float* __restrict__ bias,
         float* __restrict__ Cf, bf16* __restrict__ Chi, bf16* __restrict__ Clo,
         int Nn, int K)
{
    constexpr int OFF_AL = TM * 128;
    constexpr int OFF_BH = TM * 256;
    constexpr int BHL = TN * 128;
    constexpr int STAGEB = (TM + TN) * 256;
    constexpr int NBUF = (STAGEB >= 65536) ? 3 : 4;
    constexpr int DEPTH = NBUF - 1;
    constexpr int WARPS_M = TM / 32;
    constexpr int NWARP = NT / 32;
    constexpr int WN = TN / (NWARP / WARPS_M);
    constexpr int NG = WN / 16;
    constexpr int NJ = WN / 8;

    extern __shared__ __align__(1024) char dyns[];
    const int tid = threadIdx.x;
    const int lane = tid & 31, warp = tid >> 5;
    const int m0 = blockIdx.y * TM, n0 = blockIdx.x * TN;
    const uint32_t dbase = smem_u32(dyns);
    const int S = K >> 6;

    float acc[2][NJ][4];
#pragma unroll
    for (int a = 0; a < 2; a++)
#pragma unroll
        for (int b = 0; b < NJ; b++)
#pragma unroll
            for (int c = 0; c < 4; c++) acc[a][b][c] = 0.0f;

    auto load_stage = [&](int s) {
        const uint32_t sb = dbase + (s % NBUF) * STAGEB;
        const int k0 = s << 6;
#pragma unroll
        for (int i = 0; i < TM * 8 / NT; i++) {
            int q = tid + i * NT;
            int r = q >> 3, c = q & 7;
            uint32_t so = SWZ((uint32_t)(r * 128 + c * 16));
            size_t ga = (size_t)(m0 + r) * K + k0 + c * 8;
            cpa16(sb + so, Ah + ga);
            cpa16(sb + OFF_AL + so, Al + ga);
        }
#pragma unroll
        for (int i = 0; i < TN * 8 / NT; i++) {
            int q = tid + i * NT;
            int r = q >> 3, c = q & 7;
            uint32_t so = SWZ((uint32_t)(r * 128 + c * 16));
            size_t gb = (size_t)(n0 + r) * K + k0 + c * 8;
            cpa16(sb + OFF_BH + so, Bh + gb);
            cpa16(sb + OFF_BH + BHL + so, Bl + gb);
        }
        asm volatile("cp.async.commit_group;" ::: "memory");
    };

#pragma unroll
    for (int s = 0; s < DEPTH; s++) load_stage(s);

    const int wm = (warp % WARPS_M) * 32, wn = (warp / WARPS_M) * WN;
    const uint32_t frow = (lane & 7) + ((lane >> 3) & 1) * 8;
    const uint32_t fxor = (frow & 7) << 4;
    const uint32_t fcol = (lane >> 4) << 4;

    for (int s = 0; s < S; s++) {
        asm volatile("cp.async.wait_group %0;" :: "n"(DEPTH - 1) : "memory");
        __syncthreads();
        if (s + DEPTH < S) load_stage(s + DEPTH);
        else asm volatile("cp.async.commit_group;" ::: "memory");

        const uint32_t sb = dbase + (s % NBUF) * STAGEB;
#pragma unroll
        for (int ks = 0; ks < 4; ks++) {
            const uint32_t kc = (uint32_t)(ks * 32 + fcol) ^ fxor;
            uint32_t ahb[2][4], alb[2][4], bhb[NG][4], blb[NG][4];
#pragma unroll
            for (int mi = 0; mi < 2; mi++) {
                uint32_t ra = sb + (wm + mi * 16 + frow) * 128 + kc;
                LDSM_X4(ahb[mi][0], ahb[mi][1], ahb[mi][2], ahb[mi][3], ra);
                LDSM_X4(alb[mi][0], alb[mi][1], alb[mi][2], alb[mi][3], ra + OFF_AL);
            }
#pragma unroll
            for (int ni = 0; ni < NG; ni++) {
                uint32_t rb = sb + OFF_BH + (wn + ni * 16 + frow) * 128 + kc;
                LDSM_X4(bhb[ni][0], bhb[ni][1], bhb[ni][2], bhb[ni][3], rb);
                LDSM_X4(blb[ni][0], blb[ni][1], blb[ni][2], blb[ni][3], rb + BHL);
            }
#pragma unroll
            for (int mi = 0; mi < 2; mi++)
#pragma unroll
                for (int nj = 0; nj < NJ; nj++)
                    MMA_BF16(acc[mi][nj], ahb[mi], bhb[nj >> 1][nj & 1], bhb[nj >> 1][(nj & 1) + 2]);
#pragma unroll
            for (int mi = 0; mi < 2; mi++)
#pragma unroll
                for (int nj = 0; nj < NJ; nj++)
                    MMA_BF16(acc[mi][nj], ahb[mi], blb[nj >> 1][nj & 1], blb[nj >> 1][(nj & 1) + 2]);
#pragma unroll
            for (int mi = 0; mi < 2; mi++)
#pragma unroll
                for (int nj = 0; nj < NJ; nj++)
                    MMA_BF16(acc[mi][nj], alb[mi], bhb[nj >> 1][nj & 1], bhb[nj >> 1][(nj & 1) + 2]);
        }
    }

    // ---------------- epilogue ------------------------------------------------
    const int gr = lane >> 2, gc = lane & 3;
    const bool second = DUAL && (m0 >= Dm);
#pragma unroll
    for (int mi = 0; mi < 2; mi++) {
#pragma unroll
        for (int half = 0; half < 2; half++) {
            const int m = m0 + wm + mi * 16 + gr + half * 8;
            const int mrow = second ? (m - Dm) : m;
            float bm = 0.0f;
            if ((EPI == 1 || EPI == 2) && BIASROW) bm = bias[m];
#pragma unroll
            for (int nj = 0; nj < NJ; nj++) {
                const int n = n0 + wn + nj * 8 + 2 * gc;
                float v0 = acc[mi][nj][half * 2 + 0];
                float v1 = acc[mi][nj][half * 2 + 1];
                if (EPI == 1 || EPI == 2) {
                    if (BIASROW) { v0 += bm; v1 += bm; }
                    else         { v0 += bias[n]; v1 += bias[n + 1]; }
                }
                if (EPI == 2 || (DUAL && second)) {
                    v0 *= sigmoidf_(v0); v1 *= sigmoidf_(v1);
                }
                if (EPI == 3) {
                    v0 = fmaxf(v0, 0.0f) + log1pf(expf(-fabsf(v0)));
                    v1 = fmaxf(v1, 0.0f) + log1pf(expf(-fabsf(v1)));
                }
                size_t idx = (size_t)mrow * Nn + n;
                const bool wf = WF32 && !(DUAL && second);
                const bool ws = (WSPLIT && !DUAL) || (DUAL && second);
                if (wf) *(float2*)&Cf[idx] = make_float2(v0, v1);
                if (ws) {
                    bf16 h0 = __float2bfloat16(v0);
                    bf16 h1 = __float2bfloat16(v1);
                    __nv_bfloat162 hh; hh.x = h0; hh.y = h1;
                    __nv_bfloat162 ll;
                    ll.x = __float2bfloat16(v0 - __bfloat162float(h0));
                    ll.y = __float2bfloat16(v1 - __bfloat162float(h1));
                    *(__nv_bfloat162*)&Chi[idx] = hh;
                    *(__nv_bfloat162*)&Clo[idx] = ll;
                }
            }
        }
    }
}

// ---------------- B/C projections: [L,D] @ [D,16] ---------------------------
__global__ void __launch_bounds__(256) bc_kernel(const float* __restrict__ Xc,
                                                 const float* __restrict__ WB,
                                                 const float* __restrict__ WC,
                                                 float* __restrict__ Bo,
                                                 float* __restrict__ Co) {
    __shared__ float row[Dm];
    const int l = blockIdx.x;
    for (int k = threadIdx.x; k < Dm; k += 256) row[k] = Xc[(size_t)l * Dm + k];
    __syncthreads();
    const int part = threadIdx.x & 7;
    const int out = threadIdx.x >> 3;   // 0..31
    const int n = out & 15;
    const float* W = (out < 16) ? WB : WC;
    float s = 0.0f;
    for (int k = part; k < Dm; k += 8) s = fmaf(row[k], W[k * Ns + n], s);
#pragma unroll
    for (int off = 4; off; off >>= 1) s += __shfl_down_sync(0xffffffffu, s, off, 8);
    if (part == 0) {
        if (out < 16) Bo[l * Ns + n] = s;
        else          Co[l * Ns + n] = s;
    }
}

// ---------------- selective scan v5: smem-staged operands --------------------
// Thread per (d,n): grid 128 x 128 threads (8 d x 16 n per block).
// delta/xc/B/C staged through shared memory in 64-step chunks via cp.async,
// double-buffered -> L2 latency amortized over 64 steps instead of per-step.
constexpr int SCH = 64;                 // l-steps per chunk
constexpr int SNC = Dm / SCH;           // 16 chunks

__global__ void __launch_bounds__(128) scan_kernel(const float* __restrict__ delta,
                                                   const float* __restrict__ Xc,
                                                   const float* __restrict__ Bm,
                                                   const float* __restrict__ Cm,
                                                   const float* __restrict__ Alog,
                                                   bf16* __restrict__ Yhi,
                                                   bf16* __restrict__ Ylo) {
    __shared__ float sD[2][SCH][8];
    __shared__ float sX[2][SCH][8];
    __shared__ float sB[2][SCH][16];
    __shared__ float sC[2][SCH][16];

    const int tid = threadIdx.x;
    const int n = tid & 15;
    const int dl = tid >> 4;            // 0..7
    const int d0 = blockIdx.x * 8;
    const int d = d0 + dl;
    const float a = -expf(Alog[d * Ns + n]);

    auto load_chunk = [&](int c) {
        const int buf = c & 1;
        const int l0 = c * SCH;
        // delta & xc: per l, 8 floats (32B) = 2 x 16B. 128 tasks each.
        {
            int j = tid >> 1, hq = tid & 1;
            const size_t src = (size_t)(l0 + j) * Dm + d0 + hq * 4;
            cpa16(smem_u32(&sD[buf][j][hq * 4]), delta + src);
            cpa16(smem_u32(&sX[buf][j][hq * 4]), Xc + src);
        }
        // B & C: per l, 16 floats (64B) = 4 x 16B. 256 tasks each.
#pragma unroll
        for (int i = 0; i < 2; i++) {
            int task = tid + i * 128;
            int j = task >> 2, q = task & 3;
            cpa16(smem_u32(&sB[buf][j][q * 4]), Bm + (size_t)(l0 + j) * Ns + q * 4);
            cpa16(smem_u32(&sC[buf][j][q * 4]), Cm + (size_t)(l0 + j) * Ns + q * 4);
        }
        asm volatile("cp.async.commit_group;" ::: "memory");
    };

    load_chunk(0);
    float h = 0.0f;

    for (int c = 0; c < SNC; c++) {
        const int buf = c & 1;
        if (c + 1 < SNC) {
            load_chunk(c + 1);                                      // into buf^1 (safe: barrier at end of prev iter)
            asm volatile("cp.async.wait_group 1;" ::: "memory");    // chunk c done, c+1 in flight
        } else {
            asm volatile("cp.async.wait_group 0;" ::: "memory");
        }
        __syncthreads();

#pragma unroll 4
        for (int j = 0; j < SCH; j++) {
            float de = sD[buf][j][dl];
            float xv = sX[buf][j][dl];
            float bv = sB[buf][j][n];
            float cv = sC[buf][j][n];
            float e = __expf(de * a);
            h = fmaf(e, h, de * xv * bv);
            float pr = h * cv;
#pragma unroll
            for (int off = 8; off; off >>= 1)
                pr += __shfl_down_sync(0xffffffffu, pr, off, 16);
            if (n == 0) {
                const size_t ix = (size_t)(c * SCH + j) * Dm + d;
                bf16 hh = __float2bfloat16(pr);
                Yhi[ix] = hh;
                Ylo[ix] = __float2bfloat16(pr - __bfloat162float(hh));
            }
        }
        __syncthreads();   // all warps done with buf before it is overwritten
    }
}

// ---------------- launch ------------------------------------------------------
extern "C" void kernel_launch(void* const* d_in, const int* in_sizes, int n_in,
                              void* d_out, int out_size) {
    const float* x    = (const float*)d_in[0];
    const float* Wp   = (const float*)d_in[1];
    const float* bp   = (const float*)d_in[2];
    const float* cw   = (const float*)d_in[3];
    const float* cb   = (const float*)d_in[4];
    const float* Alog = (const float*)d_in[5];
    const float* Wd   = (const float*)d_in[6];
    const float* WB   = (const float*)d_in[7];
    const float* WC   = (const float*)d_in[8];
    float* out = (float*)d_out;

    bf16 *xhi, *xlo, *Wphi, *Wplo, *cwhi, *cwlo, *WdThi, *WdTlo;
    bf16 *xghi, *xglo, *cBhi, *cBlo, *xchi, *xclo, *yhi, *ylo, *thi, *tlo;
    float *p0, *xc, *del, *Bm, *Cm;
    cudaGetSymbolAddress((void**)&xhi, g_xhi);   cudaGetSymbolAddress((void**)&xlo, g_xlo);
    cudaGetSymbolAddress((void**)&Wphi, g_Wphi); cudaGetSymbolAddress((void**)&Wplo, g_Wplo);
    cudaGetSymbolAddress((void**)&cwhi, g_cwhi); cudaGetSymbolAddress((void**)&cwlo, g_cwlo);
    cudaGetSymbolAddress((void**)&WdThi, g_WdThi); cudaGetSymbolAddress((void**)&WdTlo, g_WdTlo);
    cudaGetSymbolAddress((void**)&xghi, g_xghi); cudaGetSymbolAddress((void**)&xglo, g_xglo);
    cudaGetSymbolAddress((void**)&cBhi, g_cBhi); cudaGetSymbolAddress((void**)&cBlo, g_cBlo);
    cudaGetSymbolAddress((void**)&xchi, g_xchi); cudaGetSymbolAddress((void**)&xclo, g_xclo);
    cudaGetSymbolAddress((void**)&yhi, g_yhi);   cudaGetSymbolAddress((void**)&ylo, g_ylo);
    cudaGetSymbolAddress((void**)&thi, g_thi);   cudaGetSymbolAddress((void**)&tlo, g_tlo);
    cudaGetSymbolAddress((void**)&p0, g_p0);
    cudaGetSymbolAddress((void**)&xc, g_xc);
    cudaGetSymbolAddress((void**)&del, g_delta);
    cudaGetSymbolAddress((void**)&Bm, g_Bm);
    cudaGetSymbolAddress((void**)&Cm, g_Cm);

    const int SMEM128 = 3 * 65536;  // proj: TM=128,TN=128, 3 buffers
    const int SMEM64  = 4 * 49152;  // squares: TM=128,TN=64, 4 buffers
    cudaFuncSetAttribute(gemm_mma<512, 128, 128, 1, false, true,  true,  true>,  cudaFuncAttributeMaxDynamicSharedMemorySize, SMEM128);
    cudaFuncSetAttribute(gemm_mma<256, 128, 64,  2, true,  true,  true,  false>, cudaFuncAttributeMaxDynamicSharedMemorySize, SMEM64);
    cudaFuncSetAttribute(gemm_mma<256, 128, 64,  3, false, true,  false, false>, cudaFuncAttributeMaxDynamicSharedMemorySize, SMEM64);
    cudaFuncSetAttribute(gemm_mma<256, 128, 64,  0, false, false, true,  false>, cudaFuncAttributeMaxDynamicSharedMemorySize, SMEM64);
    cudaFuncSetAttribute(gemm_mma<256, 128, 64,  1, false, true,  false, false>, cudaFuncAttributeMaxDynamicSharedMemorySize, SMEM64);

    // #1..#3: splits needed by the proj GEMM
    split_k<<<(2 * Dm * Dm) / 2048, 256>>>(x, xhi, xlo, 2 * Dm * Dm);
    split_k<<<(Dm * Dm) / 2048, 256>>>(Wp, Wphi, Wplo, Dm * Dm);
    transpose_split_k<<<dim3(32, 32), dim3(32, 8)>>>(Wd, WdThi, WdTlo);

    // #4 (ncu slot, control): fused input projections, M=2048, 128x128, 512 thr
    gemm_mma<512, 128, 128, 1, false, true, true, true><<<dim3(8, 16), 512, SMEM128>>>(
        xhi, xlo, Wphi, Wplo, bp, p0, xghi, xglo, Dm, Dm);

    // conv operand prep
    split_k<<<(Dm * KC) / 2048, 256>>>(cw, cwhi, cwlo, Dm * KC);
    conv_b_build<<<dim3(32, 32), 256>>>(p0, cBhi, cBlo);

    // conv as GEMM (K = 3072), 128x64 tiles, 256 thr
    gemm_mma<256, 128, 64, 2, true, true, true, false><<<dim3(16, 8), 256, SMEM64>>>(
        cwhi, cwlo, cBhi, cBlo, cb, xc, xchi, xclo, Dm, KC);

    // delta = softplus(xc @ W_delta)
    gemm_mma<256, 128, 64, 3, false, true, false, false><<<dim3(16, 8), 256, SMEM64>>>(
        xchi, xclo, WdThi, WdTlo, nullptr, del, nullptr, nullptr, Dm, Dm);

    // B, C projections + scan (smem-staged)
    bc_kernel<<<Dm, 256>>>(xc, WB, WC, Bm, Cm);
    scan_kernel<<<Dm / 8, 128>>>(del, xc, Bm, Cm, Alog, yhi, ylo);

    // t = y @ xg^T
    gemm_mma<256, 128, 64, 0, false, false, true, false><<<dim3(16, 8), 256, SMEM64>>>(
        yhi, ylo, xghi, xglo, nullptr, nullptr, thi, tlo, Dm, Dm);

    // out = t @ Wp^T + b
    gemm_mma<256, 128, 64, 1, false, true, false, false><<<dim3(16, 8), 256, SMEM64>>>(
        thi, tlo, Wphi, Wplo, bp, out, nullptr, nullptr, Dm, Dm);
}

// round 13
// speedup vs baseline: 1.2143x; 1.0204x over previous
#include <cuda_runtime.h>
#include <cuda_bf16.h>
#include <math.h>
#include <stdint.h>

constexpr int Dm = 1024;   // dim == seq len L
constexpr int Ns = 16;     // SSM state size
constexpr int KC = 3 * Dm; // conv GEMM K = 3072

typedef __nv_bfloat16 bf16;

// ---------------- scratch (static device globals: allocation-free) ----------
__device__ bf16 g_xhi[2 * Dm * Dm], g_xlo[2 * Dm * Dm];
__device__ bf16 g_Wphi[Dm * Dm],   g_Wplo[Dm * Dm];
__device__ bf16 g_cwhi[Dm * KC],   g_cwlo[Dm * KC];
__device__ bf16 g_WdThi[Dm * Dm],  g_WdTlo[Dm * Dm];
__device__ float g_p0[Dm * Dm];
__device__ bf16 g_xghi[Dm * Dm],   g_xglo[Dm * Dm];
__device__ bf16 g_cBhi[Dm * KC],   g_cBlo[Dm * KC];
__device__ float g_xc[Dm * Dm];
__device__ bf16 g_xchi[Dm * Dm],   g_xclo[Dm * Dm];
__device__ float g_delta[Dm * Dm];
__device__ float g_Bm[Dm * Ns], g_Cm[Dm * Ns];
__device__ bf16 g_yhi[Dm * Dm],    g_ylo[Dm * Dm];
__device__ bf16 g_thi[Dm * Dm],    g_tlo[Dm * Dm];

__device__ __forceinline__ float sigmoidf_(float x) {
    return 1.0f / (1.0f + expf(-x));
}

__device__ __forceinline__ uint32_t smem_u32(const void* p) {
    uint32_t a;
    asm("{ .reg .u64 t; cvta.to.shared.u64 t, %1; cvt.u32.u64 %0, t; }" : "=r"(a) : "l"(p));
    return a;
}

#define SWZ(x) ((x) ^ (((x) >> 3) & 0x70))

__device__ __forceinline__ void cpa16(uint32_t dst, const void* src) {
    asm volatile("cp.async.cg.shared.global [%0], [%1], 16;" :: "r"(dst), "l"(src));
}

#define MMA_BF16(c, a, b0, b1)                                                   \
    asm volatile(                                                                \
        "mma.sync.aligned.m16n8k16.row.col.f32.bf16.bf16.f32 "                   \
        "{%0,%1,%2,%3},{%4,%5,%6,%7},{%8,%9},{%0,%1,%2,%3};"                     \
        : "+f"(c[0]), "+f"(c[1]), "+f"(c[2]), "+f"(c[3])                         \
        : "r"(a[0]), "r"(a[1]), "r"(a[2]), "r"(a[3]), "r"(b0), "r"(b1))

#define LDSM_X4(r0, r1, r2, r3, addr)                                            \
    asm volatile("ldmatrix.sync.aligned.m8n8.x4.shared.b16 {%0,%1,%2,%3}, [%4];" \
        : "=r"(r0), "=r"(r1), "=r"(r2), "=r"(r3) : "r"(addr))

// ---------------- fused prep: all input splits + W_delta transpose -----------
// blockIdx ranges:
//   [0,1024)      split x        (2M elems, 2048/block)
//   [1024,1536)   split Wp       (1M elems)
//   [1536,2560)   transpose+split Wd (32x32 tiles)
//   [2560,4096)   split cw       (3M elems)
__device__ __forceinline__ void split_body(const float* __restrict__ in,
                                           bf16* __restrict__ hi,
                                           bf16* __restrict__ lo,
                                           int blk) {
    int i = (blk * 256 + threadIdx.x) * 8;
    float4 v0 = *(const float4*)(in + i);
    float4 v1 = *(const float4*)(in + i + 4);
    float vv[8] = {v0.x, v0.y, v0.z, v0.w, v1.x, v1.y, v1.z, v1.w};
    __nv_bfloat162 hb[4], lb[4];
#pragma unroll
    for (int j = 0; j < 4; j++) {
        bf16 h0 = __float2bfloat16(vv[2 * j]);
        bf16 h1 = __float2bfloat16(vv[2 * j + 1]);
        hb[j].x = h0; hb[j].y = h1;
        lb[j].x = __float2bfloat16(vv[2 * j] - __bfloat162float(h0));
        lb[j].y = __float2bfloat16(vv[2 * j + 1] - __bfloat162float(h1));
    }
    *(int4*)(hi + i) = *(int4*)hb;
    *(int4*)(lo + i) = *(int4*)lb;
}

__global__ void __launch_bounds__(256) prep_fused(
    const float* __restrict__ x,  bf16* __restrict__ xhi,  bf16* __restrict__ xlo,
    const float* __restrict__ Wp, bf16* __restrict__ Wphi, bf16* __restrict__ Wplo,
    const float* __restrict__ Wd, bf16* __restrict__ WdThi, bf16* __restrict__ WdTlo,
    const float* __restrict__ cw, bf16* __restrict__ cwhi, bf16* __restrict__ cwlo)
{
    const int b = blockIdx.x;
    if (b < 1024) {
        split_body(x, xhi, xlo, b);
    } else if (b < 1536) {
        split_body(Wp, Wphi, Wplo, b - 1024);
    } else if (b < 2560) {
        __shared__ float t[32][33];
        int bi = b - 1536;
        int x0 = (bi & 31) * 32, y0 = (bi >> 5) * 32;
        int tx = threadIdx.x & 31, ty0 = threadIdx.x >> 5;
        for (int j = ty0; j < 32; j += 8)
            t[j][tx] = Wd[(y0 + j) * Dm + x0 + tx];
        __syncthreads();
        for (int j = ty0; j < 32; j += 8) {
            float v = t[tx][j];
            bf16 h = __float2bfloat16(v);
            size_t idx = (size_t)(x0 + j) * Dm + y0 + tx;
            WdThi[idx] = h;
            WdTlo[idx] = __float2bfloat16(v - __bfloat162float(h));
        }
    } else {
        split_body(cw, cwhi, cwlo, b - 2560);
    }
}

// ---------------- build conv B matrix: B[d, i*3+kk] = p0[i, d-1+kk] ----------
__global__ void __launch_bounds__(256) conv_b_build(const float* __restrict__ P0,
                                                    bf16* __restrict__ hi,
                                                    bf16* __restrict__ lo) {
    __shared__ float Xs[32][35];
    int d0 = blockIdx.x * 32, i0 = blockIdx.y * 32;
    int tid = threadIdx.x;
    for (int idx = tid; idx < 32 * 34; idx += 256) {
        int r = idx / 34, c = idx % 34;
        int gd = d0 - 1 + c;
        Xs[r][c] = (gd >= 0 && gd < Dm) ? P0[(size_t)(i0 + r) * Dm + gd] : 0.0f;
    }
    __syncthreads();
    int i = tid & 31;
    for (int dl = tid >> 5; dl < 32; dl += 8) {
        size_t base = (size_t)(d0 + dl) * KC + (size_t)(i0 + i) * 3;
#pragma unroll
        for (int kk = 0; kk < 3; kk++) {
            float x = Xs[i][dl + kk];
            bf16 h = __float2bfloat16(x);
            hi[base + kk] = h;
            lo[base + kk] = __float2bfloat16(x - __bfloat162float(h));
        }
    }
}

// ---------------- bf16-split HMMA GEMM, deep cp.async pipeline ---------------
// C[m,n] = sum_k A[m,k]*B[n,k]; A=Ah+Al, B=Bh+Bl; C ~= Ah*Bh + Ah*Bl + Al*Bh.
template <int NT, int TM, int TN, int EPI, bool BIASROW, bool WF32, bool WSPLIT,
          bool DUAL>
__global__ void __launch_bounds__(NT, 1)
gemm_mma(const bf16* __restrict__ Ah, const bf16* __restrict__ Al,
         const bf16* __restrict__ Bh, const bf16* __restrict__ Bl,
         const float* __restrict__ bias,
         float* __restrict__ Cf, bf16* __restrict__ Chi, bf16* __restrict__ Clo,
         int Nn, int K)
{
    constexpr int OFF_AL = TM * 128;
    constexpr int OFF_BH = TM * 256;
    constexpr int BHL = TN * 128;
    constexpr int STAGEB = (TM + TN) * 256;
    constexpr int NBUF = (STAGEB >= 65536) ? 3 : 4;
    constexpr int DEPTH = NBUF - 1;
    constexpr int WARPS_M = TM / 32;
    constexpr int NWARP = NT / 32;
    constexpr int WN = TN / (NWARP / WARPS_M);
    constexpr int NG = WN / 16;
    constexpr int NJ = WN / 8;

    extern __shared__ __align__(1024) char dyns[];
    const int tid = threadIdx.x;
    const int lane = tid & 31, warp = tid >> 5;
    const int m0 = blockIdx.y * TM, n0 = blockIdx.x * TN;
    const uint32_t dbase = smem_u32(dyns);
    const int S = K >> 6;

    float acc[2][NJ][4];
#pragma unroll
    for (int a = 0; a < 2; a++)
#pragma unroll
        for (int b = 0; b < NJ; b++)
#pragma unroll
            for (int c = 0; c < 4; c++) acc[a][b][c] = 0.0f;

    auto load_stage = [&](int s) {
        const uint32_t sb = dbase + (s % NBUF) * STAGEB;
        const int k0 = s << 6;
#pragma unroll
        for (int i = 0; i < TM * 8 / NT; i++) {
            int q = tid + i * NT;
            int r = q >> 3, c = q & 7;
            uint32_t so = SWZ((uint32_t)(r * 128 + c * 16));
            size_t ga = (size_t)(m0 + r) * K + k0 + c * 8;
            cpa16(sb + so, Ah + ga);
            cpa16(sb + OFF_AL + so, Al + ga);
        }
#pragma unroll
        for (int i = 0; i < TN * 8 / NT; i++) {
            int q = tid + i * NT;
            int r = q >> 3, c = q & 7;
            uint32_t so = SWZ((uint32_t)(r * 128 + c * 16));
            size_t gb = (size_t)(n0 + r) * K + k0 + c * 8;
            cpa16(sb + OFF_BH + so, Bh + gb);
            cpa16(sb + OFF_BH + BHL + so, Bl + gb);
        }
        asm volatile("cp.async.commit_group;" ::: "memory");
    };

#pragma unroll
    for (int s = 0; s < DEPTH; s++) load_stage(s);

    const int wm = (warp % WARPS_M) * 32, wn = (warp / WARPS_M) * WN;
    const uint32_t frow = (lane & 7) + ((lane >> 3) & 1) * 8;
    const uint32_t fxor = (frow & 7) << 4;
    const uint32_t fcol = (lane >> 4) << 4;

    for (int s = 0; s < S; s++) {
        asm volatile("cp.async.wait_group %0;" :: "n"(DEPTH - 1) : "memory");
        __syncthreads();
        if (s + DEPTH < S) load_stage(s + DEPTH);
        else asm volatile("cp.async.commit_group;" ::: "memory");

        const uint32_t sb = dbase + (s % NBUF) * STAGEB;
#pragma unroll
        for (int ks = 0; ks < 4; ks++) {
            const uint32_t kc = (uint32_t)(ks * 32 + fcol) ^ fxor;
            uint32_t ahb[2][4], alb[2][4], bhb[NG][4], blb[NG][4];
#pragma unroll
            for (int mi = 0; mi < 2; mi++) {
                uint32_t ra = sb + (wm + mi * 16 + frow) * 128 + kc;
                LDSM_X4(ahb[mi][0], ahb[mi][1], ahb[mi][2], ahb[mi][3], ra);
                LDSM_X4(alb[mi][0], alb[mi][1], alb[mi][2], alb[mi][3], ra + OFF_AL);
            }
#pragma unroll
            for (int ni = 0; ni < NG; ni++) {
                uint32_t rb = sb + OFF_BH + (wn + ni * 16 + frow) * 128 + kc;
                LDSM_X4(bhb[ni][0], bhb[ni][1], bhb[ni][2], bhb[ni][3], rb);
                LDSM_X4(blb[ni][0], blb[ni][1], blb[ni][2], blb[ni][3], rb + BHL);
            }
#pragma unroll
            for (int mi = 0; mi < 2; mi++)
#pragma unroll
                for (int nj = 0; nj < NJ; nj++)
                    MMA_BF16(acc[mi][nj], ahb[mi], bhb[nj >> 1][nj & 1], bhb[nj >> 1][(nj & 1) + 2]);
#pragma unroll
            for (int mi = 0; mi < 2; mi++)
#pragma unroll
                for (int nj = 0; nj < NJ; nj++)
                    MMA_BF16(acc[mi][nj], ahb[mi], blb[nj >> 1][nj & 1], blb[nj >> 1][(nj & 1) + 2]);
#pragma unroll
            for (int mi = 0; mi < 2; mi++)
#pragma unroll
                for (int nj = 0; nj < NJ; nj++)
                    MMA_BF16(acc[mi][nj], alb[mi], bhb[nj >> 1][nj & 1], bhb[nj >> 1][(nj & 1) + 2]);
        }
    }

    // ---------------- epilogue ------------------------------------------------
    const int gr = lane >> 2, gc = lane & 3;
    const bool second = DUAL && (m0 >= Dm);
#pragma unroll
    for (int mi = 0; mi < 2; mi++) {
#pragma unroll
        for (int half = 0; half < 2; half++) {
            const int m = m0 + wm + mi * 16 + gr + half * 8;
            const int mrow = second ? (m - Dm) : m;
            float bm = 0.0f;
            if ((EPI == 1 || EPI == 2) && BIASROW) bm = bias[m];
#pragma unroll
            for (int nj = 0; nj < NJ; nj++) {
                const int n = n0 + wn + nj * 8 + 2 * gc;
                float v0 = acc[mi][nj][half * 2 + 0];
                float v1 = acc[mi][nj][half * 2 + 1];
                if (EPI == 1 || EPI == 2) {
                    if (BIASROW) { v0 += bm; v1 += bm; }
                    else         { v0 += bias[n]; v1 += bias[n + 1]; }
                }
                if (EPI == 2 || (DUAL && second)) {
                    v0 *= sigmoidf_(v0); v1 *= sigmoidf_(v1);
                }
                if (EPI == 3) {
                    v0 = fmaxf(v0, 0.0f) + log1pf(expf(-fabsf(v0)));
                    v1 = fmaxf(v1, 0.0f) + log1pf(expf(-fabsf(v1)));
                }
                size_t idx = (size_t)mrow * Nn + n;
                const bool wf = WF32 && !(DUAL && second);
                const bool ws = (WSPLIT && !DUAL) || (DUAL && second);
                if (wf) *(float2*)&Cf[idx] = make_float2(v0, v1);
                if (ws) {
                    bf16 h0 = __float2bfloat16(v0);
                    bf16 h1 = __float2bfloat16(v1);
                    __nv_bfloat162 hh; hh.x = h0; hh.y = h1;
                    __nv_bfloat162 ll;
                    ll.x = __float2bfloat16(v0 - __bfloat162float(h0));
                    ll.y = __float2bfloat16(v1 - __bfloat162float(h1));
                    *(__nv_bfloat162*)&Chi[idx] = hh;
                    *(__nv_bfloat162*)&Clo[idx] = ll;
                }
            }
        }
    }
}

// ---------------- B/C projections: [L,D] @ [D,16] ---------------------------
__global__ void __launch_bounds__(256) bc_kernel(const float* __restrict__ Xc,
                                                 const float* __restrict__ WB,
                                                 const float* __restrict__ WC,
                                                 float* __restrict__ Bo,
                                                 float* __restrict__ Co) {
    __shared__ float row[Dm];
    const int l = blockIdx.x;
    for (int k = threadIdx.x; k < Dm; k += 256) row[k] = Xc[(size_t)l * Dm + k];
    __syncthreads();
    const int part = threadIdx.x & 7;
    const int out = threadIdx.x >> 3;   // 0..31
    const int n = out & 15;
    const float* W = (out < 16) ? WB : WC;
    float s = 0.0f;
    for (int k = part; k < Dm; k += 8) s = fmaf(row[k], W[k * Ns + n], s);
#pragma unroll
    for (int off = 4; off; off >>= 1) s += __shfl_down_sync(0xffffffffu, s, off, 8);
    if (part == 0) {
        if (out < 16) Bo[l * Ns + n] = s;
        else          Co[l * Ns + n] = s;
    }
}

// ---------------- selective scan v5: smem-staged operands --------------------
constexpr int SCH = 64;
constexpr int SNC = Dm / SCH;

__global__ void __launch_bounds__(128) scan_kernel(const float* __restrict__ delta,
                                                   const float* __restrict__ Xc,
                                                   const float* __restrict__ Bm,
                                                   const float* __restrict__ Cm,
                                                   const float* __restrict__ Alog,
                                                   bf16* __restrict__ Yhi,
                                                   bf16* __restrict__ Ylo) {
    __shared__ float sD[2][SCH][8];
    __shared__ float sX[2][SCH][8];
    __shared__ float sB[2][SCH][16];
    __shared__ float sC[2][SCH][16];

    const int tid = threadIdx.x;
    const int n = tid & 15;
    const int dl = tid >> 4;
    const int d0 = blockIdx.x * 8;
    const int d = d0 + dl;
    const float a = -expf(Alog[d * Ns + n]);

    auto load_chunk = [&](int c) {
        const int buf = c & 1;
        const int l0 = c * SCH;
        {
            int j = tid >> 1, hq = tid & 1;
            const size_t src = (size_t)(l0 + j) * Dm + d0 + hq * 4;
            cpa16(smem_u32(&sD[buf][j][hq * 4]), delta + src);
            cpa16(smem_u32(&sX[buf][j][hq * 4]), Xc + src);
        }
#pragma unroll
        for (int i = 0; i < 2; i++) {
            int task = tid + i * 128;
            int j = task >> 2, q = task & 3;
            cpa16(smem_u32(&sB[buf][j][q * 4]), Bm + (size_t)(l0 + j) * Ns + q * 4);
            cpa16(smem_u32(&sC[buf][j][q * 4]), Cm + (size_t)(l0 + j) * Ns + q * 4);
        }
        asm volatile("cp.async.commit_group;" ::: "memory");
    };

    load_chunk(0);
    float h = 0.0f;

    for (int c = 0; c < SNC; c++) {
        const int buf = c & 1;
        if (c + 1 < SNC) {
            load_chunk(c + 1);
            asm volatile("cp.async.wait_group 1;" ::: "memory");
        } else {
            asm volatile("cp.async.wait_group 0;" ::: "memory");
        }
        __syncthreads();

#pragma unroll 4
        for (int j = 0; j < SCH; j++) {
            float de = sD[buf][j][dl];
            float xv = sX[buf][j][dl];
            float bv = sB[buf][j][n];
            float cv = sC[buf][j][n];
            float e = __expf(de * a);
            h = fmaf(e, h, de * xv * bv);
            float pr = h * cv;
#pragma unroll
            for (int off = 8; off; off >>= 1)
                pr += __shfl_down_sync(0xffffffffu, pr, off, 16);
            if (n == 0) {
                const size_t ix = (size_t)(c * SCH + j) * Dm + d;
                bf16 hh = __float2bfloat16(pr);
                Yhi[ix] = hh;
                Ylo[ix] = __float2bfloat16(pr - __bfloat162float(hh));
            }
        }
        __syncthreads();
    }
}

// ---------------- launch ------------------------------------------------------
extern "C" void kernel_launch(void* const* d_in, const int* in_sizes, int n_in,
                              void* d_out, int out_size) {
    const float* x    = (const float*)d_in[0];
    const float* Wp   = (const float*)d_in[1];
    const float* bp   = (const float*)d_in[2];
    const float* cw   = (const float*)d_in[3];
    const float* cb   = (const float*)d_in[4];
    const float* Alog = (const float*)d_in[5];
    const float* Wd   = (const float*)d_in[6];
    const float* WB   = (const float*)d_in[7];
    const float* WC   = (const float*)d_in[8];
    float* out = (float*)d_out;

    bf16 *xhi, *xlo, *Wphi, *Wplo, *cwhi, *cwlo, *WdThi, *WdTlo;
    bf16 *xghi, *xglo, *cBhi, *cBlo, *xchi, *xclo, *yhi, *ylo, *thi, *tlo;
    float *p0, *xc, *del, *Bm, *Cm;
    cudaGetSymbolAddress((void**)&xhi, g_xhi);   cudaGetSymbolAddress((void**)&xlo, g_xlo);
    cudaGetSymbolAddress((void**)&Wphi, g_Wphi); cudaGetSymbolAddress((void**)&Wplo, g_Wplo);
    cudaGetSymbolAddress((void**)&cwhi, g_cwhi); cudaGetSymbolAddress((void**)&cwlo, g_cwlo);
    cudaGetSymbolAddress((void**)&WdThi, g_WdThi); cudaGetSymbolAddress((void**)&WdTlo, g_WdTlo);
    cudaGetSymbolAddress((void**)&xghi, g_xghi); cudaGetSymbolAddress((void**)&xglo, g_xglo);
    cudaGetSymbolAddress((void**)&cBhi, g_cBhi); cudaGetSymbolAddress((void**)&cBlo, g_cBlo);
    cudaGetSymbolAddress((void**)&xchi, g_xchi); cudaGetSymbolAddress((void**)&xclo, g_xclo);
    cudaGetSymbolAddress((void**)&yhi, g_yhi);   cudaGetSymbolAddress((void**)&ylo, g_ylo);
    cudaGetSymbolAddress((void**)&thi, g_thi);   cudaGetSymbolAddress((void**)&tlo, g_tlo);
    cudaGetSymbolAddress((void**)&p0, g_p0);
    cudaGetSymbolAddress((void**)&xc, g_xc);
    cudaGetSymbolAddress((void**)&del, g_delta);
    cudaGetSymbolAddress((void**)&Bm, g_Bm);
    cudaGetSymbolAddress((void**)&Cm, g_Cm);

    const int SMEM128 = 3 * 65536;  // proj: TM=128,TN=128, 3 buffers
    const int SMEM64  = 4 * 49152;  // squares/conv: TM=128,TN=64, 4 buffers
    cudaFuncSetAttribute(gemm_mma<512, 128, 128, 1, false, true,  true,  true>,  cudaFuncAttributeMaxDynamicSharedMemorySize, SMEM128);
    cudaFuncSetAttribute(gemm_mma<256, 128, 64,  2, true,  true,  true,  false>, cudaFuncAttributeMaxDynamicSharedMemorySize, SMEM64);
    cudaFuncSetAttribute(gemm_mma<256, 128, 64,  3, false, true,  false, false>, cudaFuncAttributeMaxDynamicSharedMemorySize, SMEM64);
    cudaFuncSetAttribute(gemm_mma<256, 128, 64,  0, false, false, true,  false>, cudaFuncAttributeMaxDynamicSharedMemorySize, SMEM64);
    cudaFuncSetAttribute(gemm_mma<256, 128, 64,  1, false, true,  false, false>, cudaFuncAttributeMaxDynamicSharedMemorySize, SMEM64);

    // #1: ALL independent prep in one launch (x, Wp, Wd^T, cw splits)
    prep_fused<<<4096, 256>>>(x, xhi, xlo, Wp, Wphi, Wplo, Wd, WdThi, WdTlo,
                              cw, cwhi, cwlo);

    // #2: fused input projections, M=2048, 128x128, 512 thr, 1 wave
    gemm_mma<512, 128, 128, 1, false, true, true, true><<<dim3(8, 16), 512, SMEM128>>>(
        xhi, xlo, Wphi, Wplo, bp, p0, xghi, xglo, Dm, Dm);

    // #3: conv B operand build
    conv_b_build<<<dim3(32, 32), 256>>>(p0, cBhi, cBlo);

    // #4 (ncu slot): conv as GEMM (K = 3072), 128x64 tiles, 256 thr
    gemm_mma<256, 128, 64, 2, true, true, true, false><<<dim3(16, 8), 256, SMEM64>>>(
        cwhi, cwlo, cBhi, cBlo, cb, xc, xchi, xclo, Dm, KC);

    // delta = softplus(xc @ W_delta)
    gemm_mma<256, 128, 64, 3, false, true, false, false><<<dim3(16, 8), 256, SMEM64>>>(
        xchi, xclo, WdThi, WdTlo, nullptr, del, nullptr, nullptr, Dm, Dm);

    // B, C projections + scan (smem-staged)
    bc_kernel<<<Dm, 256>>>(xc, WB, WC, Bm, Cm);
    scan_kernel<<<Dm / 8, 128>>>(del, xc, Bm, Cm, Alog, yhi, ylo);

    // t = y @ xg^T
    gemm_mma<256, 128, 64, 0, false, false, true, false><<<dim3(16, 8), 256, SMEM64>>>(
        yhi, ylo, xghi, xglo, nullptr, nullptr, thi, tlo, Dm, Dm);

    // out = t @ Wp^T + b
    gemm_mma<256, 128, 64, 1, false, true, false, false><<<dim3(16, 8), 256, SMEM64>>>(
        thi, tlo, Wphi, Wplo, bp, out, nullptr, nullptr, Dm, Dm);
}

// round 14
// speedup vs baseline: 1.3650x; 1.1241x over previous
#include <cuda_runtime.h>
#include <cuda_bf16.h>
#include <math.h>
#include <stdint.h>

constexpr int Dm = 1024;   // dim == seq len L
constexpr int Ns = 16;     // SSM state size
constexpr int KC = 3 * Dm; // conv GEMM K = 3072

typedef __nv_bfloat16 bf16;

// ---------------- scratch (static device globals: allocation-free) ----------
__device__ bf16 g_xhi[2 * Dm * Dm], g_xlo[2 * Dm * Dm];
__device__ bf16 g_Wphi[Dm * Dm],   g_Wplo[Dm * Dm];
__device__ bf16 g_cwhi[Dm * KC],   g_cwlo[Dm * KC];
__device__ bf16 g_WdThi[Dm * Dm],  g_WdTlo[Dm * Dm];
__device__ float g_p0[Dm * Dm];
__device__ float g_xgf[Dm * Dm];    // xg fp32 (for int8 quant)
__device__ bf16 g_cBhi[Dm * KC],   g_cBlo[Dm * KC];
__device__ float g_xc[Dm * Dm];
__device__ bf16 g_xchi[Dm * Dm],   g_xclo[Dm * Dm];
__device__ float g_delta[Dm * Dm];
__device__ float g_Bm[Dm * Ns], g_Cm[Dm * Ns];
__device__ float g_yf[Dm * Dm];     // y fp32 (for int8 quant)
__device__ int8_t g_yq1[Dm * Dm],  g_yq2[Dm * Dm];
__device__ int8_t g_xgq1[Dm * Dm], g_xgq2[Dm * Dm];
__device__ float g_scy[Dm], g_scxg[Dm];
__device__ bf16 g_thi[Dm * Dm],    g_tlo[Dm * Dm];

__device__ __forceinline__ float sigmoidf_(float x) {
    return 1.0f / (1.0f + expf(-x));
}

__device__ __forceinline__ uint32_t smem_u32(const void* p) {
    uint32_t a;
    asm("{ .reg .u64 t; cvta.to.shared.u64 t, %1; cvt.u32.u64 %0, t; }" : "=r"(a) : "l"(p));
    return a;
}

#define SWZ(x) ((x) ^ (((x) >> 3) & 0x70))

__device__ __forceinline__ void cpa16(uint32_t dst, const void* src) {
    asm volatile("cp.async.cg.shared.global [%0], [%1], 16;" :: "r"(dst), "l"(src));
}

#define MMA_BF16(c, a, b0, b1)                                                   \
    asm volatile(                                                                \
        "mma.sync.aligned.m16n8k16.row.col.f32.bf16.bf16.f32 "                   \
        "{%0,%1,%2,%3},{%4,%5,%6,%7},{%8,%9},{%0,%1,%2,%3};"                     \
        : "+f"(c[0]), "+f"(c[1]), "+f"(c[2]), "+f"(c[3])                         \
        : "r"(a[0]), "r"(a[1]), "r"(a[2]), "r"(a[3]), "r"(b0), "r"(b1))

#define MMA_S8(c, a, b0, b1)                                                     \
    asm volatile(                                                                \
        "mma.sync.aligned.m16n8k32.row.col.s32.s8.s8.s32 "                       \
        "{%0,%1,%2,%3},{%4,%5,%6,%7},{%8,%9},{%0,%1,%2,%3};"                     \
        : "+r"(c[0]), "+r"(c[1]), "+r"(c[2]), "+r"(c[3])                         \
        : "r"(a[0]), "r"(a[1]), "r"(a[2]), "r"(a[3]), "r"(b0), "r"(b1))

#define LDSM_X4(r0, r1, r2, r3, addr)                                            \
    asm volatile("ldmatrix.sync.aligned.m8n8.x4.shared.b16 {%0,%1,%2,%3}, [%4];" \
        : "=r"(r0), "=r"(r1), "=r"(r2), "=r"(r3) : "r"(addr))

// ---------------- fused prep ------------------------------------------------
__device__ __forceinline__ void split_body(const float* __restrict__ in,
                                           bf16* __restrict__ hi,
                                           bf16* __restrict__ lo,
                                           int blk) {
    int i = (blk * 256 + threadIdx.x) * 8;
    float4 v0 = *(const float4*)(in + i);
    float4 v1 = *(const float4*)(in + i + 4);
    float vv[8] = {v0.x, v0.y, v0.z, v0.w, v1.x, v1.y, v1.z, v1.w};
    __nv_bfloat162 hb[4], lb[4];
#pragma unroll
    for (int j = 0; j < 4; j++) {
        bf16 h0 = __float2bfloat16(vv[2 * j]);
        bf16 h1 = __float2bfloat16(vv[2 * j + 1]);
        hb[j].x = h0; hb[j].y = h1;
        lb[j].x = __float2bfloat16(vv[2 * j] - __bfloat162float(h0));
        lb[j].y = __float2bfloat16(vv[2 * j + 1] - __bfloat162float(h1));
    }
    *(int4*)(hi + i) = *(int4*)hb;
    *(int4*)(lo + i) = *(int4*)lb;
}

__global__ void __launch_bounds__(256) prep_fused(
    const float* __restrict__ x,  bf16* __restrict__ xhi,  bf16* __restrict__ xlo,
    const float* __restrict__ Wp, bf16* __restrict__ Wphi, bf16* __restrict__ Wplo,
    const float* __restrict__ Wd, bf16* __restrict__ WdThi, bf16* __restrict__ WdTlo,
    const float* __restrict__ cw, bf16* __restrict__ cwhi, bf16* __restrict__ cwlo)
{
    const int b = blockIdx.x;
    if (b < 1024) {
        split_body(x, xhi, xlo, b);
    } else if (b < 1536) {
        split_body(Wp, Wphi, Wplo, b - 1024);
    } else if (b < 2560) {
        __shared__ float t[32][33];
        int bi = b - 1536;
        int x0 = (bi & 31) * 32, y0 = (bi >> 5) * 32;
        int tx = threadIdx.x & 31, ty0 = threadIdx.x >> 5;
        for (int j = ty0; j < 32; j += 8)
            t[j][tx] = Wd[(y0 + j) * Dm + x0 + tx];
        __syncthreads();
        for (int j = ty0; j < 32; j += 8) {
            float v = t[tx][j];
            bf16 h = __float2bfloat16(v);
            size_t idx = (size_t)(x0 + j) * Dm + y0 + tx;
            WdThi[idx] = h;
            WdTlo[idx] = __float2bfloat16(v - __bfloat162float(h));
        }
    } else {
        split_body(cw, cwhi, cwlo, b - 2560);
    }
}

// ---------------- build conv B matrix ---------------------------------------
__global__ void __launch_bounds__(256) conv_b_build(const float* __restrict__ P0,
                                                    bf16* __restrict__ hi,
                                                    bf16* __restrict__ lo) {
    __shared__ float Xs[32][35];
    int d0 = blockIdx.x * 32, i0 = blockIdx.y * 32;
    int tid = threadIdx.x;
    for (int idx = tid; idx < 32 * 34; idx += 256) {
        int r = idx / 34, c = idx % 34;
        int gd = d0 - 1 + c;
        Xs[r][c] = (gd >= 0 && gd < Dm) ? P0[(size_t)(i0 + r) * Dm + gd] : 0.0f;
    }
    __syncthreads();
    int i = tid & 31;
    for (int dl = tid >> 5; dl < 32; dl += 8) {
        size_t base = (size_t)(d0 + dl) * KC + (size_t)(i0 + i) * 3;
#pragma unroll
        for (int kk = 0; kk < 3; kk++) {
            float x = Xs[i][dl + kk];
            bf16 h = __float2bfloat16(x);
            hi[base + kk] = h;
            lo[base + kk] = __float2bfloat16(x - __bfloat162float(h));
        }
    }
}

// ---------------- bf16-split HMMA GEMM (unchanged core) ----------------------
template <int NT, int TM, int TN, int EPI, bool BIASROW, bool WF32, bool WSPLIT,
          bool DUAL>
__global__ void __launch_bounds__(NT, 1)
gemm_mma(const bf16* __restrict__ Ah, const bf16* __restrict__ Al,
         const bf16* __restrict__ Bh, const bf16* __restrict__ Bl,
         const float* __restrict__ bias,
         float* __restrict__ Cf, bf16* __restrict__ Chi, bf16* __restrict__ Clo,
         float* __restrict__ Cf2,
         int Nn, int K)
{
    constexpr int OFF_AL = TM * 128;
    constexpr int OFF_BH = TM * 256;
    constexpr int BHL = TN * 128;
    constexpr int STAGEB = (TM + TN) * 256;
    constexpr int NBUF = (STAGEB >= 65536) ? 3 : 4;
    constexpr int DEPTH = NBUF - 1;
    constexpr int WARPS_M = TM / 32;
    constexpr int NWARP = NT / 32;
    constexpr int WN = TN / (NWARP / WARPS_M);
    constexpr int NG = WN / 16;
    constexpr int NJ = WN / 8;

    extern __shared__ __align__(1024) char dyns[];
    const int tid = threadIdx.x;
    const int lane = tid & 31, warp = tid >> 5;
    const int m0 = blockIdx.y * TM, n0 = blockIdx.x * TN;
    const uint32_t dbase = smem_u32(dyns);
    const int S = K >> 6;

    float acc[2][NJ][4];
#pragma unroll
    for (int a = 0; a < 2; a++)
#pragma unroll
        for (int b = 0; b < NJ; b++)
#pragma unroll
            for (int c = 0; c < 4; c++) acc[a][b][c] = 0.0f;

    auto load_stage = [&](int s) {
        const uint32_t sb = dbase + (s % NBUF) * STAGEB;
        const int k0 = s << 6;
#pragma unroll
        for (int i = 0; i < TM * 8 / NT; i++) {
            int q = tid + i * NT;
            int r = q >> 3, c = q & 7;
            uint32_t so = SWZ((uint32_t)(r * 128 + c * 16));
            size_t ga = (size_t)(m0 + r) * K + k0 + c * 8;
            cpa16(sb + so, Ah + ga);
            cpa16(sb + OFF_AL + so, Al + ga);
        }
#pragma unroll
        for (int i = 0; i < TN * 8 / NT; i++) {
            int q = tid + i * NT;
            int r = q >> 3, c = q & 7;
            uint32_t so = SWZ((uint32_t)(r * 128 + c * 16));
            size_t gb = (size_t)(n0 + r) * K + k0 + c * 8;
            cpa16(sb + OFF_BH + so, Bh + gb);
            cpa16(sb + OFF_BH + BHL + so, Bl + gb);
        }
        asm volatile("cp.async.commit_group;" ::: "memory");
    };

#pragma unroll
    for (int s = 0; s < DEPTH; s++) load_stage(s);

    const int wm = (warp % WARPS_M) * 32, wn = (warp / WARPS_M) * WN;
    const uint32_t frow = (lane & 7) + ((lane >> 3) & 1) * 8;
    const uint32_t fxor = (frow & 7) << 4;
    const uint32_t fcol = (lane >> 4) << 4;

    for (int s = 0; s < S; s++) {
        asm volatile("cp.async.wait_group %0;" :: "n"(DEPTH - 1) : "memory");
        __syncthreads();
        if (s + DEPTH < S) load_stage(s + DEPTH);
        else asm volatile("cp.async.commit_group;" ::: "memory");

        const uint32_t sb = dbase + (s % NBUF) * STAGEB;
#pragma unroll
        for (int ks = 0; ks < 4; ks++) {
            const uint32_t kc = (uint32_t)(ks * 32 + fcol) ^ fxor;
            uint32_t ahb[2][4], alb[2][4], bhb[NG][4], blb[NG][4];
#pragma unroll
            for (int mi = 0; mi < 2; mi++) {
                uint32_t ra = sb + (wm + mi * 16 + frow) * 128 + kc;
                LDSM_X4(ahb[mi][0], ahb[mi][1], ahb[mi][2], ahb[mi][3], ra);
                LDSM_X4(alb[mi][0], alb[mi][1], alb[mi][2], alb[mi][3], ra + OFF_AL);
            }
#pragma unroll
            for (int ni = 0; ni < NG; ni++) {
                uint32_t rb = sb + OFF_BH + (wn + ni * 16 + frow) * 128 + kc;
                LDSM_X4(bhb[ni][0], bhb[ni][1], bhb[ni][2], bhb[ni][3], rb);
                LDSM_X4(blb[ni][0], blb[ni][1], blb[ni][2], blb[ni][3], rb + BHL);
            }
#pragma unroll
            for (int mi = 0; mi < 2; mi++)
#pragma unroll
                for (int nj = 0; nj < NJ; nj++)
                    MMA_BF16(acc[mi][nj], ahb[mi], bhb[nj >> 1][nj & 1], bhb[nj >> 1][(nj & 1) + 2]);
#pragma unroll
            for (int mi = 0; mi < 2; mi++)
#pragma unroll
                for (int nj = 0; nj < NJ; nj++)
                    MMA_BF16(acc[mi][nj], ahb[mi], blb[nj >> 1][nj & 1], blb[nj >> 1][(nj & 1) + 2]);
#pragma unroll
            for (int mi = 0; mi < 2; mi++)
#pragma unroll
                for (int nj = 0; nj < NJ; nj++)
                    MMA_BF16(acc[mi][nj], alb[mi], bhb[nj >> 1][nj & 1], bhb[nj >> 1][(nj & 1) + 2]);
        }
    }

    const int gr = lane >> 2, gc = lane & 3;
    const bool second = DUAL && (m0 >= Dm);
#pragma unroll
    for (int mi = 0; mi < 2; mi++) {
#pragma unroll
        for (int half = 0; half < 2; half++) {
            const int m = m0 + wm + mi * 16 + gr + half * 8;
            const int mrow = second ? (m - Dm) : m;
            float bm = 0.0f;
            if ((EPI == 1 || EPI == 2) && BIASROW) bm = bias[m];
#pragma unroll
            for (int nj = 0; nj < NJ; nj++) {
                const int n = n0 + wn + nj * 8 + 2 * gc;
                float v0 = acc[mi][nj][half * 2 + 0];
                float v1 = acc[mi][nj][half * 2 + 1];
                if (EPI == 1 || EPI == 2) {
                    if (BIASROW) { v0 += bm; v1 += bm; }
                    else         { v0 += bias[n]; v1 += bias[n + 1]; }
                }
                if (EPI == 2 || (DUAL && second)) {
                    v0 *= sigmoidf_(v0); v1 *= sigmoidf_(v1);
                }
                if (EPI == 3) {
                    v0 = fmaxf(v0, 0.0f) + log1pf(expf(-fabsf(v0)));
                    v1 = fmaxf(v1, 0.0f) + log1pf(expf(-fabsf(v1)));
                }
                size_t idx = (size_t)mrow * Nn + n;
                if (DUAL && second) {
                    *(float2*)&Cf2[idx] = make_float2(v0, v1);
                } else {
                    if (WF32) *(float2*)&Cf[idx] = make_float2(v0, v1);
                    if (WSPLIT) {
                        bf16 h0 = __float2bfloat16(v0);
                        bf16 h1 = __float2bfloat16(v1);
                        __nv_bfloat162 hh; hh.x = h0; hh.y = h1;
                        __nv_bfloat162 ll;
                        ll.x = __float2bfloat16(v0 - __bfloat162float(h0));
                        ll.y = __float2bfloat16(v1 - __bfloat162float(h1));
                        *(__nv_bfloat162*)&Chi[idx] = hh;
                        *(__nv_bfloat162*)&Clo[idx] = ll;
                    }
                }
            }
        }
    }
}

// ---------------- int8 two-level quantization (per-row scale) ----------------
// q1 = rint(x/s), q2 = rint((x - s*q1)*256/s); x ~ s*(q1 + q2/256)
__global__ void __launch_bounds__(256) quant_rows(const float* __restrict__ A,
                                                  const float* __restrict__ B,
                                                  int8_t* __restrict__ Aq1,
                                                  int8_t* __restrict__ Aq2,
                                                  int8_t* __restrict__ Bq1,
                                                  int8_t* __restrict__ Bq2,
                                                  float* __restrict__ sA,
                                                  float* __restrict__ sB) {
    const int row = blockIdx.x;
    const bool isB = row >= Dm;
    const int r = isB ? row - Dm : row;
    const float* in = (isB ? B : A) + (size_t)r * Dm;
    int8_t* q1 = (isB ? Bq1 : Aq1) + (size_t)r * Dm;
    int8_t* q2 = (isB ? Bq2 : Aq2) + (size_t)r * Dm;
    const int tid = threadIdx.x;

    float4 v = *(const float4*)(in + tid * 4);
    float m = fmaxf(fmaxf(fabsf(v.x), fabsf(v.y)), fmaxf(fabsf(v.z), fabsf(v.w)));
    __shared__ float red[8];
#pragma unroll
    for (int off = 16; off; off >>= 1)
        m = fmaxf(m, __shfl_xor_sync(0xffffffffu, m, off));
    if ((tid & 31) == 0) red[tid >> 5] = m;
    __syncthreads();
    if (tid < 32) {
        float t2 = (tid < 8) ? red[tid] : 0.0f;
#pragma unroll
        for (int off = 4; off; off >>= 1)
            t2 = fmaxf(t2, __shfl_xor_sync(0xffffffffu, t2, off));
        if (tid == 0) {
            red[0] = fmaxf(t2, 1e-20f);
            if (isB) sB[r] = red[0] / 127.0f; else sA[r] = red[0] / 127.0f;
        }
    }
    __syncthreads();
    const float s = red[0] / 127.0f;
    const float inv = 127.0f / red[0];
    float vv[4] = {v.x, v.y, v.z, v.w};
    char c1[4], c2[4];
#pragma unroll
    for (int j = 0; j < 4; j++) {
        float qq1 = rintf(vv[j] * inv);
        float rres = vv[j] - s * qq1;
        float qq2 = fminf(fmaxf(rintf(rres * inv * 256.0f), -127.0f), 127.0f);
        c1[j] = (char)(int)qq1;
        c2[j] = (char)(int)qq2;
    }
    *(int*)(q1 + tid * 4) = *(int*)c1;
    *(int*)(q2 + tid * 4) = *(int*)c2;
}

// ---------------- int8 3-term IMMA GEMM (pilot: t = y @ xg^T) ----------------
// C[m,n] = sA[m]*sB[n]*(D11 + (D12 + D21)/256). Output: split bf16.
__global__ void __launch_bounds__(256, 1)
gemm_i8(const int8_t* __restrict__ Aq1, const int8_t* __restrict__ Aq2,
        const int8_t* __restrict__ Bq1, const int8_t* __restrict__ Bq2,
        const float* __restrict__ sA, const float* __restrict__ sB,
        bf16* __restrict__ Chi, bf16* __restrict__ Clo, int Nn, int K)
{
    constexpr int TM = 128, TN = 64, NT = 256;
    constexpr int OFF_A2 = TM * 128;
    constexpr int OFF_B1 = TM * 256;
    constexpr int BL = TN * 128;
    constexpr int STAGEB = (TM + TN) * 256;  // 48KB
    constexpr int NBUF = 4, DEPTH = 3;
    constexpr int NJ = 4, NG = 2;            // warp tile 32x32

    extern __shared__ __align__(1024) char dyns[];
    const int tid = threadIdx.x;
    const int lane = tid & 31, warp = tid >> 5;
    const int m0 = blockIdx.y * TM, n0 = blockIdx.x * TN;
    const uint32_t dbase = smem_u32(dyns);
    const int S = K >> 7;   // 128 int8 per stage

    int acc0[2][NJ][4], acc1[2][NJ][4];
#pragma unroll
    for (int a = 0; a < 2; a++)
#pragma unroll
        for (int b = 0; b < NJ; b++)
#pragma unroll
            for (int c = 0; c < 4; c++) { acc0[a][b][c] = 0; acc1[a][b][c] = 0; }

    auto load_stage = [&](int s) {
        const uint32_t sb = dbase + (s % NBUF) * STAGEB;
        const int k0 = s << 7;
#pragma unroll
        for (int i = 0; i < 4; i++) {          // A: 128 rows x 128B, 16B chunks
            int q = tid + i * NT;
            int r = q >> 3, c = q & 7;
            uint32_t so = SWZ((uint32_t)(r * 128 + c * 16));
            size_t ga = (size_t)(m0 + r) * K + k0 + c * 16;
            cpa16(sb + so, Aq1 + ga);
            cpa16(sb + OFF_A2 + so, Aq2 + ga);
        }
#pragma unroll
        for (int i = 0; i < 2; i++) {          // B: 64 rows x 128B
            int q = tid + i * NT;
            int r = q >> 3, c = q & 7;
            uint32_t so = SWZ((uint32_t)(r * 128 + c * 16));
            size_t gb = (size_t)(n0 + r) * K + k0 + c * 16;
            cpa16(sb + OFF_B1 + so, Bq1 + gb);
            cpa16(sb + OFF_B1 + BL + so, Bq2 + gb);
        }
        asm volatile("cp.async.commit_group;" ::: "memory");
    };

#pragma unroll
    for (int s = 0; s < DEPTH; s++) load_stage(s);

    const int wm = (warp & 3) * 32, wn = (warp >> 2) * 32;
    const uint32_t frow = (lane & 7) + ((lane >> 3) & 1) * 8;
    const uint32_t fxor = (frow & 7) << 4;
    const uint32_t fcol = (lane >> 4) << 4;

    for (int s = 0; s < S; s++) {
        asm volatile("cp.async.wait_group %0;" :: "n"(DEPTH - 1) : "memory");
        __syncthreads();
        if (s + DEPTH < S) load_stage(s + DEPTH);
        else asm volatile("cp.async.commit_group;" ::: "memory");

        const uint32_t sb = dbase + (s % NBUF) * STAGEB;
#pragma unroll
        for (int ks = 0; ks < 4; ks++) {       // 4 x k32 per stage
            const uint32_t kc = (uint32_t)(ks * 32 + fcol) ^ fxor;
            uint32_t a1[2][4], a2[2][4], b1[NG][4], b2[NG][4];
#pragma unroll
            for (int mi = 0; mi < 2; mi++) {
                uint32_t ra = sb + (wm + mi * 16 + frow) * 128 + kc;
                LDSM_X4(a1[mi][0], a1[mi][1], a1[mi][2], a1[mi][3], ra);
                LDSM_X4(a2[mi][0], a2[mi][1], a2[mi][2], a2[mi][3], ra + OFF_A2);
            }
#pragma unroll
            for (int ni = 0; ni < NG; ni++) {
                uint32_t rb = sb + OFF_B1 + (wn + ni * 16 + frow) * 128 + kc;
                LDSM_X4(b1[ni][0], b1[ni][1], b1[ni][2], b1[ni][3], rb);
                LDSM_X4(b2[ni][0], b2[ni][1], b2[ni][2], b2[ni][3], rb + BL);
            }
#pragma unroll
            for (int mi = 0; mi < 2; mi++)
#pragma unroll
                for (int nj = 0; nj < NJ; nj++)
                    MMA_S8(acc0[mi][nj], a1[mi], b1[nj >> 1][nj & 1], b1[nj >> 1][(nj & 1) + 2]);
#pragma unroll
            for (int mi = 0; mi < 2; mi++)
#pragma unroll
                for (int nj = 0; nj < NJ; nj++)
                    MMA_S8(acc1[mi][nj], a1[mi], b2[nj >> 1][nj & 1], b2[nj >> 1][(nj & 1) + 2]);
#pragma unroll
            for (int mi = 0; mi < 2; mi++)
#pragma unroll
                for (int nj = 0; nj < NJ; nj++)
                    MMA_S8(acc1[mi][nj], a2[mi], b1[nj >> 1][nj & 1], b1[nj >> 1][(nj & 1) + 2]);
        }
    }

    const int gr = lane >> 2, gc = lane & 3;
#pragma unroll
    for (int mi = 0; mi < 2; mi++) {
#pragma unroll
        for (int half = 0; half < 2; half++) {
            const int m = m0 + wm + mi * 16 + gr + half * 8;
            const float sa = sA[m];
#pragma unroll
            for (int nj = 0; nj < NJ; nj++) {
                const int n = n0 + wn + nj * 8 + 2 * gc;
                float sb0 = sB[n], sb1 = sB[n + 1];
                float v0 = sa * sb0 * ((float)acc0[mi][nj][half * 2 + 0] +
                                       (float)acc1[mi][nj][half * 2 + 0] * (1.0f / 256.0f));
                float v1 = sa * sb1 * ((float)acc0[mi][nj][half * 2 + 1] +
                                       (float)acc1[mi][nj][half * 2 + 1] * (1.0f / 256.0f));
                size_t idx = (size_t)m * Nn + n;
                bf16 h0 = __float2bfloat16(v0);
                bf16 h1 = __float2bfloat16(v1);
                __nv_bfloat162 hh; hh.x = h0; hh.y = h1;
                __nv_bfloat162 ll;
                ll.x = __float2bfloat16(v0 - __bfloat162float(h0));
                ll.y = __float2bfloat16(v1 - __bfloat162float(h1));
                *(__nv_bfloat162*)&Chi[idx] = hh;
                *(__nv_bfloat162*)&Clo[idx] = ll;
            }
        }
    }
}

// ---------------- B/C projections -------------------------------------------
__global__ void __launch_bounds__(256) bc_kernel(const float* __restrict__ Xc,
                                                 const float* __restrict__ WB,
                                                 const float* __restrict__ WC,
                                                 float* __restrict__ Bo,
                                                 float* __restrict__ Co) {
    __shared__ float row[Dm];
    const int l = blockIdx.x;
    for (int k = threadIdx.x; k < Dm; k += 256) row[k] = Xc[(size_t)l * Dm + k];
    __syncthreads();
    const int part = threadIdx.x & 7;
    const int out = threadIdx.x >> 3;
    const int n = out & 15;
    const float* W = (out < 16) ? WB : WC;
    float s = 0.0f;
    for (int k = part; k < Dm; k += 8) s = fmaf(row[k], W[k * Ns + n], s);
#pragma unroll
    for (int off = 4; off; off >>= 1) s += __shfl_down_sync(0xffffffffu, s, off, 8);
    if (part == 0) {
        if (out < 16) Bo[l * Ns + n] = s;
        else          Co[l * Ns + n] = s;
    }
}

// ---------------- selective scan v5 (fp32 y output) --------------------------
constexpr int SCH = 64;
constexpr int SNC = Dm / SCH;

__global__ void __launch_bounds__(128) scan_kernel(const float* __restrict__ delta,
                                                   const float* __restrict__ Xc,
                                                   const float* __restrict__ Bm,
                                                   const float* __restrict__ Cm,
                                                   const float* __restrict__ Alog,
                                                   float* __restrict__ Y) {
    __shared__ float sD[2][SCH][8];
    __shared__ float sX[2][SCH][8];
    __shared__ float sB[2][SCH][16];
    __shared__ float sC[2][SCH][16];

    const int tid = threadIdx.x;
    const int n = tid & 15;
    const int dl = tid >> 4;
    const int d0 = blockIdx.x * 8;
    const int d = d0 + dl;
    const float a = -expf(Alog[d * Ns + n]);

    auto load_chunk = [&](int c) {
        const int buf = c & 1;
        const int l0 = c * SCH;
        {
            int j = tid >> 1, hq = tid & 1;
            const size_t src = (size_t)(l0 + j) * Dm + d0 + hq * 4;
            cpa16(smem_u32(&sD[buf][j][hq * 4]), delta + src);
            cpa16(smem_u32(&sX[buf][j][hq * 4]), Xc + src);
        }
#pragma unroll
        for (int i = 0; i < 2; i++) {
            int task = tid + i * 128;
            int j = task >> 2, q = task & 3;
            cpa16(smem_u32(&sB[buf][j][q * 4]), Bm + (size_t)(l0 + j) * Ns + q * 4);
            cpa16(smem_u32(&sC[buf][j][q * 4]), Cm + (size_t)(l0 + j) * Ns + q * 4);
        }
        asm volatile("cp.async.commit_group;" ::: "memory");
    };

    load_chunk(0);
    float h = 0.0f;

    for (int c = 0; c < SNC; c++) {
        const int buf = c & 1;
        if (c + 1 < SNC) {
            load_chunk(c + 1);
            asm volatile("cp.async.wait_group 1;" ::: "memory");
        } else {
            asm volatile("cp.async.wait_group 0;" ::: "memory");
        }
        __syncthreads();

#pragma unroll 4
        for (int j = 0; j < SCH; j++) {
            float de = sD[buf][j][dl];
            float xv = sX[buf][j][dl];
            float bv = sB[buf][j][n];
            float cv = sC[buf][j][n];
            float e = __expf(de * a);
            h = fmaf(e, h, de * xv * bv);
            float pr = h * cv;
#pragma unroll
            for (int off = 8; off; off >>= 1)
                pr += __shfl_down_sync(0xffffffffu, pr, off, 16);
            if (n == 0)
                Y[(size_t)(c * SCH + j) * Dm + d] = pr;
        }
        __syncthreads();
    }
}

// ---------------- launch ------------------------------------------------------
extern "C" void kernel_launch(void* const* d_in, const int* in_sizes, int n_in,
                              void* d_out, int out_size) {
    const float* x    = (const float*)d_in[0];
    const float* Wp   = (const float*)d_in[1];
    const float* bp   = (const float*)d_in[2];
    const float* cw   = (const float*)d_in[3];
    const float* cb   = (const float*)d_in[4];
    const float* Alog = (const float*)d_in[5];
    const float* Wd   = (const float*)d_in[6];
    const float* WB   = (const float*)d_in[7];
    const float* WC   = (const float*)d_in[8];
    float* out = (float*)d_out;

    bf16 *xhi, *xlo, *Wphi, *Wplo, *cwhi, *cwlo, *WdThi, *WdTlo;
    bf16 *cBhi, *cBlo, *xchi, *xclo, *thi, *tlo;
    float *p0, *xgf, *xc, *del, *Bm, *Cm, *yf, *scy, *scxg;
    int8_t *yq1, *yq2, *xgq1, *xgq2;
    cudaGetSymbolAddress((void**)&xhi, g_xhi);   cudaGetSymbolAddress((void**)&xlo, g_xlo);
    cudaGetSymbolAddress((void**)&Wphi, g_Wphi); cudaGetSymbolAddress((void**)&Wplo, g_Wplo);
    cudaGetSymbolAddress((void**)&cwhi, g_cwhi); cudaGetSymbolAddress((void**)&cwlo, g_cwlo);
    cudaGetSymbolAddress((void**)&WdThi, g_WdThi); cudaGetSymbolAddress((void**)&WdTlo, g_WdTlo);
    cudaGetSymbolAddress((void**)&cBhi, g_cBhi); cudaGetSymbolAddress((void**)&cBlo, g_cBlo);
    cudaGetSymbolAddress((void**)&xchi, g_xchi); cudaGetSymbolAddress((void**)&xclo, g_xclo);
    cudaGetSymbolAddress((void**)&thi, g_thi);   cudaGetSymbolAddress((void**)&tlo, g_tlo);
    cudaGetSymbolAddress((void**)&p0, g_p0);
    cudaGetSymbolAddress((void**)&xgf, g_xgf);
    cudaGetSymbolAddress((void**)&xc, g_xc);
    cudaGetSymbolAddress((void**)&del, g_delta);
    cudaGetSymbolAddress((void**)&Bm, g_Bm);
    cudaGetSymbolAddress((void**)&Cm, g_Cm);
    cudaGetSymbolAddress((void**)&yf, g_yf);
    cudaGetSymbolAddress((void**)&yq1, g_yq1);   cudaGetSymbolAddress((void**)&yq2, g_yq2);
    cudaGetSymbolAddress((void**)&xgq1, g_xgq1); cudaGetSymbolAddress((void**)&xgq2, g_xgq2);
    cudaGetSymbolAddress((void**)&scy, g_scy);   cudaGetSymbolAddress((void**)&scxg, g_scxg);

    const int SMEM128 = 3 * 65536;
    const int SMEM64  = 4 * 49152;
    cudaFuncSetAttribute(gemm_mma<512, 128, 128, 1, false, true,  false, true>,  cudaFuncAttributeMaxDynamicSharedMemorySize, SMEM128);
    cudaFuncSetAttribute(gemm_mma<256, 128, 64,  2, true,  true,  true,  false>, cudaFuncAttributeMaxDynamicSharedMemorySize, SMEM64);
    cudaFuncSetAttribute(gemm_mma<256, 128, 64,  3, false, true,  false, false>, cudaFuncAttributeMaxDynamicSharedMemorySize, SMEM64);
    cudaFuncSetAttribute(gemm_mma<256, 128, 64,  1, false, true,  false, false>, cudaFuncAttributeMaxDynamicSharedMemorySize, SMEM64);
    cudaFuncSetAttribute(gemm_i8, cudaFuncAttributeMaxDynamicSharedMemorySize, SMEM64);

    // #1: all independent prep
    prep_fused<<<4096, 256>>>(x, xhi, xlo, Wp, Wphi, Wplo, Wd, WdThi, WdTlo,
                              cw, cwhi, cwlo);

    // #2: fused input projections: p0 fp32 + xg fp32 (silu)
    gemm_mma<512, 128, 128, 1, false, true, false, true><<<dim3(8, 16), 512, SMEM128>>>(
        xhi, xlo, Wphi, Wplo, bp, p0, nullptr, nullptr, xgf, Dm, Dm);

    // #3: conv B operand build
    conv_b_build<<<dim3(32, 32), 256>>>(p0, cBhi, cBlo);

    // #4: conv as GEMM (K = 3072)
    gemm_mma<256, 128, 64, 2, true, true, true, false><<<dim3(16, 8), 256, SMEM64>>>(
        cwhi, cwlo, cBhi, cBlo, cb, xc, xchi, xclo, nullptr, Dm, KC);

    // #5: delta = softplus(xc @ W_delta)
    gemm_mma<256, 128, 64, 3, false, true, false, false><<<dim3(16, 8), 256, SMEM64>>>(
        xchi, xclo, WdThi, WdTlo, nullptr, del, nullptr, nullptr, nullptr, Dm, Dm);

    // #6-7: B/C projections + scan (fp32 y)
    bc_kernel<<<Dm, 256>>>(xc, WB, WC, Bm, Cm);
    scan_kernel<<<Dm / 8, 128>>>(del, xc, Bm, Cm, Alog, yf);

    // #8: quantize y (rows 0..1023) and xg (rows 1024..2047)
    quant_rows<<<2 * Dm, 256>>>(yf, xgf, yq1, yq2, xgq1, xgq2, scy, scxg);

    // #9: t = y @ xg^T  (int8 pilot)
    gemm_i8<<<dim3(16, 8), 256, SMEM64>>>(yq1, yq2, xgq1, xgq2, scy, scxg,
                                          thi, tlo, Dm, Dm);

    // #10: out = t @ Wp^T + b
    gemm_mma<256, 128, 64, 1, false, true, false, false><<<dim3(16, 8), 256, SMEM64>>>(
        thi, tlo, Wphi, Wplo, bp, out, nullptr, nullptr, nullptr, Dm, Dm);
}